// round 13
// baseline (speedup 1.0000x reference)
#include <cuda_runtime.h>
#include <cuda_bf16.h>
#include <cuda_fp16.h>
#include <math.h>
#include <stdint.h>

#define G_CNT 1024
#define A_CNT 20
#define N_CNT (G_CNT * A_CNT)          // 20480
#define E_CNT (G_CNT * A_CNT * A_CNT)  // 409600
#define H_DIM 128
#define NLAYER 4
#define EDGE_GRID 148

typedef unsigned long long u64;
typedef unsigned int u32;
typedef unsigned short u16;

// ---------------- scratch (device globals) ----------------
__device__ float g_h[N_CNT * H_DIM];
__device__ float g_hs[N_CNT * H_DIM];
__device__ float g_hd[N_CNT * H_DIM];
__device__ float g_agg[N_CNT * H_DIM];
__device__ float g_latip[G_CNT * 9];
__device__ float g_latterm[NLAYER * G_CNT * H_DIM];
__device__ float g_embT[100 * H_DIM];
__device__ u16 g_disH[(size_t)E_CNT * 64];
// fp16 weights, consumer-ready K-major [n][k]
__device__ u16 g_w1d[NLAYER * 128 * 64];
__device__ u16 g_w1n[NLAYER * 256 * 128];
__device__ u16 g_w2[NLAYER * 128 * 128];
__device__ u16 g_nw1[NLAYER * 128 * 256];
__device__ u16 g_nw2[NLAYER * 128 * 128];

// silu via EX2 + RCP (fast MUFU on sm_103a; tanh.approx is NOT -> R8 regression)
__device__ __forceinline__ float siluf(float x) {
    return __fdividef(x, 1.0f + __expf(-x));
}
__device__ __forceinline__ u16 h_rn(float x) {
    return __half_as_ushort(__float2half_rn(x));
}
__device__ __forceinline__ u32 pack_h2(float a, float b) {
    __half2 hh = __floats2half2_rn(a, b);
    return *(u32*)&hh;
}

__device__ __forceinline__ void mma_f16(float c[4], const u32 a[4], u32 b0, u32 b1) {
    asm volatile(
        "mma.sync.aligned.m16n8k16.row.col.f32.f16.f16.f32 "
        "{%0,%1,%2,%3}, {%4,%5,%6,%7}, {%8,%9}, {%0,%1,%2,%3};"
        : "+f"(c[0]), "+f"(c[1]), "+f"(c[2]), "+f"(c[3])
        : "r"(a[0]), "r"(a[1]), "r"(a[2]), "r"(a[3]), "r"(b0), "r"(b1));
}

// ---------------- weight prep ----------------
__global__ __launch_bounds__(256) void k_prep(
    const float* __restrict__ ew1, const float* __restrict__ ew2,
    const float* __restrict__ nw1, const float* __restrict__ nw2)
{
    int i = blockIdx.x * 256 + threadIdx.x;
    if (i >= NLAYER * 106496) return;
    int L = i / 106496, j = i % 106496;
    const float* e1 = ew1 + L * 325 * 128;
    const float* e2 = ew2 + L * 128 * 128;
    const float* n1 = nw1 + L * 256 * 128;
    const float* n2 = nw2 + L * 128 * 128;
    if (j < 8192) {
        int n = j >> 6, k = j & 63;
        float v = (k < 60) ? e1[(265 + k) * 128 + n] : 0.f;
        g_w1d[L * 8192 + j] = h_rn(v);
    } else if (j < 40960) {
        int jj = j - 8192;
        int n = jj >> 7, k = jj & 127;
        float v = (n < 128) ? e1[k * 128 + n] : e1[(128 + k) * 128 + (n - 128)];
        g_w1n[L * 32768 + jj] = h_rn(v);
    } else if (j < 57344) {
        int jj = j - 40960;
        int n = jj >> 7, k = jj & 127;
        g_w2[L * 16384 + jj] = h_rn(e2[k * 128 + n]);
    } else if (j < 90112) {
        int jj = j - 57344;
        int n = jj >> 8, k = jj & 255;
        g_nw1[L * 32768 + jj] = h_rn(n1[k * 128 + n]);
    } else {
        int jj = j - 90112;
        int n = jj >> 7, k = jj & 127;
        g_nw2[L * 16384 + jj] = h_rn(n2[k * 128 + n]);
    }
}

// ---------------- embT ----------------
__global__ __launch_bounds__(128) void k_prep_emb(
    const float* __restrict__ emb_table, const float* __restrict__ w_latent)
{
    int a = blockIdx.x, c = threadIdx.x;
    float s = 0.f;
#pragma unroll 4
    for (int k = 0; k < 128; ++k)
        s = fmaf(emb_table[a * 128 + k], w_latent[k * 128 + c], s);
    g_embT[a * 128 + c] = s;
}

// ---------------- lat_ip ----------------
__global__ void k_latip(const float* __restrict__ lattices) {
    int g = blockIdx.x, tid = threadIdx.x;
    if (tid < 9) {
        int i = tid / 3, k = tid % 3;
        float s = 0.f;
#pragma unroll
        for (int j = 0; j < 3; ++j)
            s += lattices[g * 9 + i * 3 + j] * lattices[g * 9 + k * 3 + j];
        g_latip[g * 9 + tid] = s;
    }
}

// ---------------- latterm for ALL layers, once ----------------
__global__ __launch_bounds__(256) void k_latall(
    const float* __restrict__ ew1, const float* __restrict__ eb1)
{
    int idx = blockIdx.x * 256 + threadIdx.x;
    int L = idx >> 17;
    int g = (idx >> 7) & (G_CNT - 1);
    int c = idx & 127;
    float lt = eb1[L * 128 + c];
#pragma unroll
    for (int j = 0; j < 9; ++j)
        lt += g_latip[g * 9 + j] * ew1[L * 325 * 128 + (256 + j) * 128 + c];
    g_latterm[idx] = lt;
}

// ---------------- dis embedding ----------------
__global__ __launch_bounds__(128) void k_dis(const float* __restrict__ fc) {
    __shared__ u32 hiS[128 * 33];
    int tid = threadIdx.x;
    size_t e0 = (size_t)blockIdx.x * 128;
    int e = (int)e0 + tid;
    int g = e / 400, r = e % 400;
    int src = g * 20 + r / 20;
    int dst = g * 20 + r % 20;
    u16* hrow = (u16*)(hiS + tid * 33);
#pragma unroll
    for (int c = 0; c < 3; ++c) {
        float d = fc[dst * 3 + c] - fc[src * 3 + c];
        d -= floorf(d);
        float s1, c1;
        sincospif(2.0f * d, &s1, &c1);
        float s = 0.f, co = 1.f;
        hrow[c * 10] = 0;
        hrow[30 + c * 10] = h_rn(1.f);
#pragma unroll
        for (int f = 1; f < 10; ++f) {
            float ns = s * c1 + co * s1;
            float nc = co * c1 - s * s1;
            s = ns; co = nc;
            hrow[c * 10 + f] = h_rn(s);
            hrow[30 + c * 10 + f] = h_rn(co);
        }
    }
#pragma unroll
    for (int k = 60; k < 64; ++k) hrow[k] = 0;
    __syncthreads();
    u32* gh = (u32*)g_disH + e0 * 32;
    for (int i = tid; i < 4096; i += 128)
        gh[i] = hiS[(i >> 5) * 33 + (i & 31)];
}

// ---------------- node embedding ----------------
__global__ __launch_bounds__(128) void k_embed(
    const int* __restrict__ atom_types, const float* __restrict__ t,
    const float* __restrict__ w_latent, const float* __restrict__ b_latent)
{
    __shared__ int at[20];
    __shared__ float ts[256];
    int g = blockIdx.x, c = threadIdx.x;
    if (c < 20) at[c] = atom_types[g * 20 + c];
    ts[c] = t[g * 256 + c];
    ts[c + 128] = t[g * 256 + c + 128];
    __syncthreads();
    float t0 = b_latent[c], t1 = 0.f, t2 = 0.f, t3 = 0.f;
#pragma unroll 8
    for (int k = 0; k < 256; k += 4) {
        t0 = fmaf(ts[k],     w_latent[(128 + k) * 128 + c], t0);
        t1 = fmaf(ts[k + 1], w_latent[(129 + k) * 128 + c], t1);
        t2 = fmaf(ts[k + 2], w_latent[(130 + k) * 128 + c], t2);
        t3 = fmaf(ts[k + 3], w_latent[(131 + k) * 128 + c], t3);
    }
    float tl = (t0 + t1) + (t2 + t3);
#pragma unroll
    for (int n = 0; n < 20; ++n)
        g_h[(g * 20 + n) * H_DIM + c] = g_embT[at[n] * 128 + c] + tl;
}

// ---------------- tensor nodeside (every layer), 4 graphs/block ----------
#define NS4A 0                      // A 80*272 = 21760
#define NS4B 21760                  // B 256*272 = 69632
#define NS4_TOT 91392

__global__ __launch_bounds__(256, 2) void k_nodeside_t4(int L)
{
    extern __shared__ char sm[];
    int gb = blockIdx.x, tid = threadIdx.x;
    int w = tid >> 5, lane = tid & 31;
    int gq = lane >> 2, tig = lane & 3;

    for (int idx = tid; idx < 5120; idx += 256) {
        int r = idx >> 6, c2 = idx & 63;
        const float* src = g_h + ((size_t)gb * 80 + r) * 128 + c2 * 2;
        *(u32*)(sm + NS4A + r * 272 + c2 * 4) = pack_h2(src[0], src[1]);
    }
    {
        const u32* src = (const u32*)(g_w1n + L * 32768);
        for (int idx = tid; idx < 16384; idx += 256) {
            int n = idx >> 6, k2 = idx & 63;
            *(u32*)(sm + NS4B + n * 272 + k2 * 4) = src[idx];
        }
    }
    __syncthreads();

    int njb = w * 4;
    float acc[5][4][4];
#pragma unroll
    for (int m = 0; m < 5; ++m)
#pragma unroll
        for (int j = 0; j < 4; ++j)
            acc[m][j][0] = acc[m][j][1] = acc[m][j][2] = acc[m][j][3] = 0.f;

#pragma unroll
    for (int ks = 0; ks < 8; ++ks) {
        int kc = ks * 16 + 2 * tig;
        u32 bh[4][2];
#pragma unroll
        for (int j = 0; j < 4; ++j) {
            const char* b = sm + NS4B + ((njb + j) * 8 + gq) * 272 + kc * 2;
            bh[j][0] = *(const u32*)b;
            bh[j][1] = *(const u32*)(b + 16);
        }
#pragma unroll
        for (int m = 0; m < 5; ++m) {
            u32 ah[4];
            const char* Ab = sm + NS4A + (m * 16) * 272;
            ah[0] = *(const u32*)(Ab + gq * 272 + kc * 2);
            ah[1] = *(const u32*)(Ab + (gq + 8) * 272 + kc * 2);
            ah[2] = *(const u32*)(Ab + gq * 272 + (kc + 8) * 2);
            ah[3] = *(const u32*)(Ab + (gq + 8) * 272 + (kc + 8) * 2);
#pragma unroll
            for (int j = 0; j < 4; ++j)
                mma_f16(acc[m][j], ah, bh[j][0], bh[j][1]);
        }
    }
#pragma unroll
    for (int m = 0; m < 5; ++m) {
        int rowA = m * 16 + gq, rowB = rowA + 8;
#pragma unroll
        for (int j = 0; j < 4; ++j) {
            int n = (njb + j) * 8 + 2 * tig;
            size_t baseA = ((size_t)gb * 80 + rowA) * 128;
            size_t baseB = ((size_t)gb * 80 + rowB) * 128;
            float* dA = (n < 128) ? (g_hs + baseA + n) : (g_hd + baseA + n - 128);
            float* dB = (n < 128) ? (g_hs + baseB + n) : (g_hd + baseB + n - 128);
            *(float2*)dA = make_float2(acc[m][j][0], acc[m][j][1]);
            *(float2*)dB = make_float2(acc[m][j][2], acc[m][j][3]);
        }
    }
}

// ---------------- persistent edge kernel, graph PAIRS ----------------
#define SW1 0           // 18432
#define SW2 18432       // 34816 -> 53248
#define SAW 53248       // 16 x 4352 -> 122880
#define SHS 122880      // 2 graphs x 10240 -> 143360
#define SHD 143360      // 20480 -> 163840
#define SB2 163840      // 512 -> 164352
#define SPART 164352    // 50 tiles x 2 x 128 f32 = 51200 -> 215552
#define SM_TOT 215552

__global__ __launch_bounds__(512, 1) void k_edge_p(
    int L, const float* __restrict__ eb2)
{
    extern __shared__ char sm[];
    int tid = threadIdx.x;
    int w = tid >> 5, lane = tid & 31;
    int gq = lane >> 2, tig = lane & 3;

    {
        const u32* src = (const u32*)(g_w1d + L * 8192);
        for (int idx = tid; idx < 4096; idx += 512) {
            int n = idx >> 5, k2 = idx & 31;
            *(u32*)(sm + SW1 + n * 144 + k2 * 4) = src[idx];
        }
        const u32* src2 = (const u32*)(g_w2 + L * 16384);
        for (int idx = tid; idx < 8192; idx += 512) {
            int n = idx >> 6, k2 = idx & 63;
            *(u32*)(sm + SW2 + n * 272 + k2 * 4) = src2[idx];
        }
        if (tid < 128) ((float*)(sm + SB2))[tid] = eb2[tid];
    }

    float* hs = (float*)(sm + SHS);
    float* hd = (float*)(sm + SHD);
    float* b2 = (float*)(sm + SB2);
    float* part = (float*)(sm + SPART);
    char* AB = sm + SAW + w * 4352;
    const float* lat4 = g_latterm + (size_t)L * G_CNT * H_DIM;

    for (int gp = blockIdx.x; gp < G_CNT / 2; gp += EDGE_GRID) {
        __syncthreads();
        for (int i = tid; i < 5120; i += 512) {
            int gg = i / 2560, c = i & 127;
            hs[i] = g_hs[(size_t)gp * 5120 + i] + lat4[(gp * 2 + gg) * 128 + c];
            hd[i] = g_hd[(size_t)gp * 5120 + i];
        }
        __syncthreads();

        for (int u = w; u < 50; u += 16) {
            int gg = u / 25, lt = u - gg * 25;
            int e0 = lt * 16;
            const float* hsg = hs + gg * 2560;
            const float* hdg = hd + gg * 2560;
            {
                const uint4* sH = (const uint4*)(g_disH +
                    ((size_t)(gp * 2 + gg) * 400 + e0) * 64);
#pragma unroll
                for (int q = 0; q < 4; ++q) {
                    int idx = lane + q * 32;
                    int row = idx >> 3, seg = idx & 7;
                    *(uint4*)(AB + row * 144 + seg * 16) = sH[row * 8 + seg];
                }
            }
            __syncwarp();

            // GEMM1
            float acc[16][4];
#pragma unroll
            for (int j = 0; j < 16; ++j)
                acc[j][0] = acc[j][1] = acc[j][2] = acc[j][3] = 0.f;
#pragma unroll
            for (int ks = 0; ks < 4; ++ks) {
                int kc = ks * 16 + 2 * tig;
                u32 ah[4];
                ah[0] = *(const u32*)(AB + gq * 144 + kc * 2);
                ah[1] = *(const u32*)(AB + (gq + 8) * 144 + kc * 2);
                ah[2] = *(const u32*)(AB + gq * 144 + (kc + 8) * 2);
                ah[3] = *(const u32*)(AB + (gq + 8) * 144 + (kc + 8) * 2);
#pragma unroll
                for (int j = 0; j < 16; ++j) {
                    const char* bh = sm + SW1 + ((j * 8 + gq) * 72 + kc) * 2;
                    mma_f16(acc[j], ah, *(const u32*)bh, *(const u32*)(bh + 16));
                }
            }
            __syncwarp();

            // epilogue A
            {
                int eA = e0 + gq, eB = e0 + gq + 8;
                int srcA = eA / 20, dstA = eA - srcA * 20;
                int srcB = eB / 20, dstB = eB - srcB * 20;
#pragma unroll
                for (int j = 0; j < 16; ++j) {
                    int c0 = j * 8 + 2 * tig;
                    float2 hsA = *(const float2*)&hsg[srcA * 128 + c0];
                    float2 hdA = *(const float2*)&hdg[dstA * 128 + c0];
                    float2 hsB = *(const float2*)&hsg[srcB * 128 + c0];
                    float2 hdB = *(const float2*)&hdg[dstB * 128 + c0];
                    float x0 = siluf(acc[j][0] + hsA.x + hdA.x);
                    float x1 = siluf(acc[j][1] + hsA.y + hdA.y);
                    float x2 = siluf(acc[j][2] + hsB.x + hdB.x);
                    float x3 = siluf(acc[j][3] + hsB.y + hdB.y);
                    *(u32*)(AB + gq * 272 + c0 * 2) = pack_h2(x0, x1);
                    *(u32*)(AB + (gq + 8) * 272 + c0 * 2) = pack_h2(x2, x3);
                }
            }
            __syncwarp();

            // GEMM2
            float acc2[16][4];
#pragma unroll
            for (int j = 0; j < 16; ++j)
                acc2[j][0] = acc2[j][1] = acc2[j][2] = acc2[j][3] = 0.f;
#pragma unroll
            for (int ks = 0; ks < 8; ++ks) {
                int kc = ks * 16 + 2 * tig;
                u32 ah[4];
                ah[0] = *(const u32*)(AB + gq * 272 + kc * 2);
                ah[1] = *(const u32*)(AB + (gq + 8) * 272 + kc * 2);
                ah[2] = *(const u32*)(AB + gq * 272 + (kc + 8) * 2);
                ah[3] = *(const u32*)(AB + (gq + 8) * 272 + (kc + 8) * 2);
#pragma unroll
                for (int j = 0; j < 16; ++j) {
                    const char* bh = sm + SW2 + ((j * 8 + gq) * 136 + kc) * 2;
                    mma_f16(acc2[j], ah, *(const u32*)bh, *(const u32*)(bh + 16));
                }
            }

            // epilogue B
            {
                float* ef = (float*)AB;
                int sA = e0 / 20;
                int bnd = 20 * (sA + 1) - e0;
                if (bnd > 16) bnd = 16;
#pragma unroll
                for (int half = 0; half < 2; ++half) {
                    __syncwarp();
#pragma unroll
                    for (int j = half * 8; j < half * 8 + 8; ++j) {
                        int c0 = j * 8 + 2 * tig;
                        float2 bb = *(const float2*)&b2[c0];
                        float2 v0, v1;
                        v0.x = siluf(acc2[j][0] + bb.x);
                        v0.y = siluf(acc2[j][1] + bb.y);
                        v1.x = siluf(acc2[j][2] + bb.x);
                        v1.y = siluf(acc2[j][3] + bb.y);
                        int cl = c0 - half * 64;
                        *(float2*)&ef[gq * 68 + cl] = v0;
                        *(float2*)&ef[(gq + 8) * 68 + cl] = v1;
                    }
                    __syncwarp();
                    int cl = 2 * lane;
                    float2 p0 = make_float2(0.f, 0.f), p1 = make_float2(0.f, 0.f);
#pragma unroll
                    for (int r = 0; r < 16; ++r) {
                        float2 v = *(const float2*)&ef[r * 68 + cl];
                        if (r < bnd) { p0.x += v.x; p0.y += v.y; }
                        else { p1.x += v.x; p1.y += v.y; }
                    }
                    *(float2*)&part[u * 256 + half * 64 + cl] = p0;
                    *(float2*)&part[u * 256 + 128 + half * 64 + cl] = p1;
                }
            }
            __syncwarp();
        }
        __syncthreads();

        // combine partials -> scatter-mean (both graphs)
        for (int idx = tid; idx < 5120; idx += 512) {
            int gg = idx / 2560, r = idx - gg * 2560;
            int s = r >> 7, c = r & 127;
            int t0 = (20 * s) >> 4, t1 = (20 * s + 19) >> 4;
            float a = 0.f;
            for (int t = t0; t <= t1; ++t) {
                int sA = (16 * t) / 20;
                int sB = (16 * t + 15) / 20;
                int tg = gg * 25 + t;
                if (sA == s) a += part[tg * 256 + c];
                else if (sB == s) a += part[tg * 256 + 128 + c];
            }
            g_agg[(size_t)gp * 5120 + idx] = a * 0.05f;
        }
    }
}

// ---------------- tensor node MLP + residual, 8 graphs/block (R11 proven) --
#define M8A1 0          // 160*528 = 84480
#define M8B1 84480      // 128*528 -> 152064
#define M8A2 0          // aliases A1
#define M8B2 43520      // aliases A1
#define M8_TOT 152064

__global__ __launch_bounds__(256, 1) void k_nodemlp_t8(
    int L, const float* __restrict__ nb1, const float* __restrict__ nb2)
{
    extern __shared__ char sm[];
    int gb = blockIdx.x, tid = threadIdx.x;
    int w = tid >> 5, lane = tid & 31;
    int gq = lane >> 2, tig = lane & 3;

    for (int idx = tid; idx < 20480; idx += 256) {
        int r = idx >> 7, c2 = idx & 127;
        float a0, a1;
        size_t base = ((size_t)gb * 160 + r) * 128;
        if (c2 < 64) {
            const float* s = g_h + base + c2 * 2;
            a0 = s[0]; a1 = s[1];
        } else {
            const float* s = g_agg + base + (c2 - 64) * 2;
            a0 = s[0]; a1 = s[1];
        }
        *(u32*)(sm + M8A1 + r * 528 + c2 * 4) = pack_h2(a0, a1);
    }
    {
        const u32* src = (const u32*)(g_nw1 + L * 32768);
        for (int idx = tid; idx < 16384; idx += 256) {
            int n = idx >> 7, k2 = idx & 127;
            *(u32*)(sm + M8B1 + n * 528 + k2 * 4) = src[idx];
        }
    }
    __syncthreads();

    int njb = w * 2;
    float acc[10][2][4];
#pragma unroll
    for (int m = 0; m < 10; ++m)
#pragma unroll
        for (int j = 0; j < 2; ++j)
            acc[m][j][0] = acc[m][j][1] = acc[m][j][2] = acc[m][j][3] = 0.f;
#pragma unroll
    for (int ks = 0; ks < 16; ++ks) {
        int kc = ks * 16 + 2 * tig;
        u32 bh[2][2];
#pragma unroll
        for (int j = 0; j < 2; ++j) {
            const char* b = sm + M8B1 + ((njb + j) * 8 + gq) * 528 + kc * 2;
            bh[j][0] = *(const u32*)b;
            bh[j][1] = *(const u32*)(b + 16);
        }
#pragma unroll
        for (int m = 0; m < 10; ++m) {
            u32 ah[4];
            const char* Ab = sm + M8A1 + (m * 16) * 528;
            ah[0] = *(const u32*)(Ab + gq * 528 + kc * 2);
            ah[1] = *(const u32*)(Ab + (gq + 8) * 528 + kc * 2);
            ah[2] = *(const u32*)(Ab + gq * 528 + (kc + 8) * 2);
            ah[3] = *(const u32*)(Ab + (gq + 8) * 528 + (kc + 8) * 2);
#pragma unroll
            for (int j = 0; j < 2; ++j)
                mma_f16(acc[m][j], ah, bh[j][0], bh[j][1]);
        }
    }
    __syncthreads();   // A1/B1 dead -> overwrite with A2/B2

#pragma unroll
    for (int m = 0; m < 10; ++m) {
        int rA = m * 16 + gq;
#pragma unroll
        for (int j = 0; j < 2; ++j) {
            int c0 = (njb + j) * 8 + 2 * tig;
            float bb0 = __ldg(nb1 + c0), bb1 = __ldg(nb1 + c0 + 1);
            *(u32*)(sm + M8A2 + rA * 272 + c0 * 2) =
                pack_h2(siluf(acc[m][j][0] + bb0), siluf(acc[m][j][1] + bb1));
            *(u32*)(sm + M8A2 + (rA + 8) * 272 + c0 * 2) =
                pack_h2(siluf(acc[m][j][2] + bb0), siluf(acc[m][j][3] + bb1));
        }
    }
    {
        const u32* src2 = (const u32*)(g_nw2 + L * 16384);
        for (int idx = tid; idx < 8192; idx += 256) {
            int n = idx >> 6, k2 = idx & 63;
            *(u32*)(sm + M8B2 + n * 272 + k2 * 4) = src2[idx];
        }
    }
    __syncthreads();

    float acc2[10][2][4];
#pragma unroll
    for (int m = 0; m < 10; ++m)
#pragma unroll
        for (int j = 0; j < 2; ++j)
            acc2[m][j][0] = acc2[m][j][1] = acc2[m][j][2] = acc2[m][j][3] = 0.f;
#pragma unroll
    for (int ks = 0; ks < 8; ++ks) {
        int kc = ks * 16 + 2 * tig;
        u32 bh[2][2];
#pragma unroll
        for (int j = 0; j < 2; ++j) {
            const char* b = sm + M8B2 + ((njb + j) * 8 + gq) * 272 + kc * 2;
            bh[j][0] = *(const u32*)b;
            bh[j][1] = *(const u32*)(b + 16);
        }
#pragma unroll
        for (int m = 0; m < 10; ++m) {
            u32 ah[4];
            const char* Ab = sm + M8A2 + (m * 16) * 272;
            ah[0] = *(const u32*)(Ab + gq * 272 + kc * 2);
            ah[1] = *(const u32*)(Ab + (gq + 8) * 272 + kc * 2);
            ah[2] = *(const u32*)(Ab + gq * 272 + (kc + 8) * 2);
            ah[3] = *(const u32*)(Ab + (gq + 8) * 272 + (kc + 8) * 2);
#pragma unroll
            for (int j = 0; j < 2; ++j)
                mma_f16(acc2[m][j], ah, bh[j][0], bh[j][1]);
        }
    }
#pragma unroll
    for (int m = 0; m < 10; ++m) {
        int rA = m * 16 + gq, rB = rA + 8;
#pragma unroll
        for (int j = 0; j < 2; ++j) {
            int c0 = (njb + j) * 8 + 2 * tig;
            float bb0 = __ldg(nb2 + c0), bb1 = __ldg(nb2 + c0 + 1);
            {
                float* d = g_h + ((size_t)gb * 160 + rA) * 128 + c0;
                float2 o = *(float2*)d;
                o.x += siluf(acc2[m][j][0] + bb0);
                o.y += siluf(acc2[m][j][1] + bb1);
                *(float2*)d = o;
            }
            {
                float* d = g_h + ((size_t)gb * 160 + rB) * 128 + c0;
                float2 o = *(float2*)d;
                o.x += siluf(acc2[m][j][2] + bb0);
                o.y += siluf(acc2[m][j][3] + bb1);
                *(float2*)d = o;
            }
        }
    }
}

// ---------------- output heads ----------------
__global__ __launch_bounds__(128) void k_final(
    const float* __restrict__ lattices, const float* __restrict__ coord_w,
    const float* __restrict__ lattice_w, float* __restrict__ out)
{
    __shared__ __align__(16) float hT[128 * 20];
    __shared__ float gf[128];
    __shared__ float pre[9];
    int g = blockIdx.x, tid = threadIdx.x;
    for (int n = 0; n < 20; ++n)
        hT[tid * 20 + n] = g_h[(g * 20 + n) * H_DIM + tid];
    __syncthreads();
    float s = 0.f;
#pragma unroll
    for (int n = 0; n < 20; ++n) s += hT[tid * 20 + n];
    gf[tid] = s * 0.05f;
    __syncthreads();
    if (tid < 9) {
        float acc = 0.f;
        for (int k = 0; k < 128; ++k) acc += gf[k] * lattice_w[k * 9 + tid];
        pre[tid] = acc;
    }
    __syncthreads();
    if (tid < 9) {
        int i = tid / 3, kk = tid % 3;
        float v = 0.f;
#pragma unroll
        for (int j = 0; j < 3; ++j)
            v += pre[i * 3 + j] * lattices[g * 9 + j * 3 + kk];
        out[g * 9 + tid] = v;
    }
    if (tid < 60) {
        int n = tid / 3, c = tid % 3;
        float acc = 0.f;
        for (int k = 0; k < 128; ++k) acc += hT[k * 20 + n] * coord_w[k * 3 + c];
        out[G_CNT * 9 + (g * 20 + n) * 3 + c] = acc;
    }
}

// ---------------- launch ----------------
extern "C" void kernel_launch(void* const* d_in, const int* in_sizes, int n_in,
                              void* d_out, int out_size) {
    const int*   atom_types = (const int*)d_in[0];
    const float* frac       = (const float*)d_in[1];
    const float* lattices   = (const float*)d_in[2];
    const float* t          = (const float*)d_in[3];
    const float* emb_table  = (const float*)d_in[7];
    const float* w_latent   = (const float*)d_in[8];
    const float* b_latent   = (const float*)d_in[9];
    const float* ew1        = (const float*)d_in[10];
    const float* eb1        = (const float*)d_in[11];
    const float* ew2        = (const float*)d_in[12];
    const float* eb2        = (const float*)d_in[13];
    const float* nw1        = (const float*)d_in[14];
    const float* nb1        = (const float*)d_in[15];
    const float* nw2        = (const float*)d_in[16];
    const float* nb2        = (const float*)d_in[17];
    const float* coord_w    = (const float*)d_in[18];
    const float* lattice_w  = (const float*)d_in[19];
    float* out = (float*)d_out;

    cudaFuncSetAttribute(k_edge_p, cudaFuncAttributeMaxDynamicSharedMemorySize, SM_TOT);
    cudaFuncSetAttribute(k_nodemlp_t8, cudaFuncAttributeMaxDynamicSharedMemorySize, M8_TOT);
    cudaFuncSetAttribute(k_nodeside_t4, cudaFuncAttributeMaxDynamicSharedMemorySize, NS4_TOT);

    k_prep<<<(NLAYER * 106496 + 255) / 256, 256>>>(ew1, ew2, nw1, nw2);
    k_prep_emb<<<100, 128>>>(emb_table, w_latent);
    k_latip<<<G_CNT, 32>>>(lattices);
    k_latall<<<NLAYER * G_CNT * 128 / 256, 256>>>(ew1, eb1);
    k_embed<<<G_CNT, 128>>>(atom_types, t, w_latent, b_latent);
    k_dis<<<E_CNT / 128, 128>>>(frac);
    for (int i = 0; i < NLAYER; ++i) {
        k_nodeside_t4<<<G_CNT / 4, 256, NS4_TOT>>>(i);
        k_edge_p<<<EDGE_GRID, 512, SM_TOT>>>(i, eb2 + i * 128);
        k_nodemlp_t8<<<G_CNT / 8, 256, M8_TOT>>>(i, nb1 + i * 128, nb2 + i * 128);
    }
    k_final<<<G_CNT, 128>>>(lattices, coord_w, lattice_w, out);
}

// round 14
// speedup vs baseline: 1.1946x; 1.1946x over previous
#include <cuda_runtime.h>
#include <cuda_bf16.h>
#include <cuda_fp16.h>
#include <math.h>
#include <stdint.h>

#define G_CNT 1024
#define A_CNT 20
#define N_CNT (G_CNT * A_CNT)
#define E_CNT (G_CNT * A_CNT * A_CNT)
#define H_DIM 128
#define NLAYER 4
#define EDGE_GRID 148
#define EW_THREADS 832

typedef unsigned long long u64;
typedef unsigned int u32;
typedef unsigned short u16;

// ---------------- scratch ----------------
__device__ float g_h[N_CNT * H_DIM];
__device__ float g_hs[N_CNT * H_DIM];
__device__ float g_hd[N_CNT * H_DIM];
__device__ float g_agg[N_CNT * H_DIM];
__device__ float g_latip[G_CNT * 9];
__device__ float g_latterm[NLAYER * G_CNT * H_DIM];
__device__ float g_embT[100 * H_DIM];
__device__ u16 g_disH[(size_t)E_CNT * 64];
__device__ u16 g_w1d[NLAYER * 128 * 64];
__device__ u16 g_w1n[NLAYER * 256 * 128];
__device__ u16 g_w2[NLAYER * 128 * 128];
__device__ u16 g_nw1[NLAYER * 128 * 256];
__device__ u16 g_nw2[NLAYER * 128 * 128];

__device__ __forceinline__ float siluf(float x) {
    return __fdividef(x, 1.0f + __expf(-x));
}
__device__ __forceinline__ u16 h_rn(float x) {
    return __half_as_ushort(__float2half_rn(x));
}
__device__ __forceinline__ u32 pack_h2(float a, float b) {
    __half2 hh = __floats2half2_rn(a, b);
    return *(u32*)&hh;
}
__device__ __forceinline__ void mma_f16(float c[4], const u32 a[4], u32 b0, u32 b1) {
    asm volatile(
        "mma.sync.aligned.m16n8k16.row.col.f32.f16.f16.f32 "
        "{%0,%1,%2,%3}, {%4,%5,%6,%7}, {%8,%9}, {%0,%1,%2,%3};"
        : "+f"(c[0]), "+f"(c[1]), "+f"(c[2]), "+f"(c[3])
        : "r"(a[0]), "r"(a[1]), "r"(a[2]), "r"(a[3]), "r"(b0), "r"(b1));
}

// ---------------- weight prep ----------------
__global__ __launch_bounds__(256) void k_prep(
    const float* __restrict__ ew1, const float* __restrict__ ew2,
    const float* __restrict__ nw1, const float* __restrict__ nw2)
{
    int i = blockIdx.x * 256 + threadIdx.x;
    if (i >= NLAYER * 106496) return;
    int L = i / 106496, j = i % 106496;
    const float* e1 = ew1 + L * 325 * 128;
    const float* e2 = ew2 + L * 128 * 128;
    const float* n1 = nw1 + L * 256 * 128;
    const float* n2 = nw2 + L * 128 * 128;
    if (j < 8192) {
        int n = j >> 6, k = j & 63;
        float v = (k < 60) ? e1[(265 + k) * 128 + n] : 0.f;
        g_w1d[L * 8192 + j] = h_rn(v);
    } else if (j < 40960) {
        int jj = j - 8192;
        int n = jj >> 7, k = jj & 127;
        float v = (n < 128) ? e1[k * 128 + n] : e1[(128 + k) * 128 + (n - 128)];
        g_w1n[L * 32768 + jj] = h_rn(v);
    } else if (j < 57344) {
        int jj = j - 40960;
        int n = jj >> 7, k = jj & 127;
        g_w2[L * 16384 + jj] = h_rn(e2[k * 128 + n]);
    } else if (j < 90112) {
        int jj = j - 57344;
        int n = jj >> 8, k = jj & 255;
        g_nw1[L * 32768 + jj] = h_rn(n1[k * 128 + n]);
    } else {
        int jj = j - 90112;
        int n = jj >> 7, k = jj & 127;
        g_nw2[L * 16384 + jj] = h_rn(n2[k * 128 + n]);
    }
}

__global__ __launch_bounds__(128) void k_prep_emb(
    const float* __restrict__ emb_table, const float* __restrict__ w_latent)
{
    int a = blockIdx.x, c = threadIdx.x;
    float s = 0.f;
#pragma unroll 4
    for (int k = 0; k < 128; ++k)
        s = fmaf(emb_table[a * 128 + k], w_latent[k * 128 + c], s);
    g_embT[a * 128 + c] = s;
}

__global__ void k_latip(const float* __restrict__ lattices) {
    int g = blockIdx.x, tid = threadIdx.x;
    if (tid < 9) {
        int i = tid / 3, k = tid % 3;
        float s = 0.f;
#pragma unroll
        for (int j = 0; j < 3; ++j)
            s += lattices[g * 9 + i * 3 + j] * lattices[g * 9 + k * 3 + j];
        g_latip[g * 9 + tid] = s;
    }
}

__global__ __launch_bounds__(256) void k_latall(
    const float* __restrict__ ew1, const float* __restrict__ eb1)
{
    int idx = blockIdx.x * 256 + threadIdx.x;
    int L = idx >> 17;
    int g = (idx >> 7) & (G_CNT - 1);
    int c = idx & 127;
    float lt = eb1[L * 128 + c];
#pragma unroll
    for (int j = 0; j < 9; ++j)
        lt += g_latip[g * 9 + j] * ew1[L * 325 * 128 + (256 + j) * 128 + c];
    g_latterm[idx] = lt;
}

__global__ __launch_bounds__(128) void k_dis(const float* __restrict__ fc) {
    __shared__ u32 hiS[128 * 33];
    int tid = threadIdx.x;
    size_t e0 = (size_t)blockIdx.x * 128;
    int e = (int)e0 + tid;
    int g = e / 400, r = e % 400;
    int src = g * 20 + r / 20;
    int dst = g * 20 + r % 20;
    u16* hrow = (u16*)(hiS + tid * 33);
#pragma unroll
    for (int c = 0; c < 3; ++c) {
        float d = fc[dst * 3 + c] - fc[src * 3 + c];
        d -= floorf(d);
        float s1, c1;
        sincospif(2.0f * d, &s1, &c1);
        float s = 0.f, co = 1.f;
        hrow[c * 10] = 0;
        hrow[30 + c * 10] = h_rn(1.f);
#pragma unroll
        for (int f = 1; f < 10; ++f) {
            float ns = s * c1 + co * s1;
            float nc = co * c1 - s * s1;
            s = ns; co = nc;
            hrow[c * 10 + f] = h_rn(s);
            hrow[30 + c * 10 + f] = h_rn(co);
        }
    }
#pragma unroll
    for (int k = 60; k < 64; ++k) hrow[k] = 0;
    __syncthreads();
    u32* gh = (u32*)g_disH + e0 * 32;
    for (int i = tid; i < 4096; i += 128)
        gh[i] = hiS[(i >> 5) * 33 + (i & 31)];
}

__global__ __launch_bounds__(128) void k_embed(
    const int* __restrict__ atom_types, const float* __restrict__ t,
    const float* __restrict__ w_latent, const float* __restrict__ b_latent)
{
    __shared__ int at[20];
    __shared__ float ts[256];
    int g = blockIdx.x, c = threadIdx.x;
    if (c < 20) at[c] = atom_types[g * 20 + c];
    ts[c] = t[g * 256 + c];
    ts[c + 128] = t[g * 256 + c + 128];
    __syncthreads();
    float t0 = b_latent[c], t1 = 0.f, t2 = 0.f, t3 = 0.f;
#pragma unroll 8
    for (int k = 0; k < 256; k += 4) {
        t0 = fmaf(ts[k],     w_latent[(128 + k) * 128 + c], t0);
        t1 = fmaf(ts[k + 1], w_latent[(129 + k) * 128 + c], t1);
        t2 = fmaf(ts[k + 2], w_latent[(130 + k) * 128 + c], t2);
        t3 = fmaf(ts[k + 3], w_latent[(131 + k) * 128 + c], t3);
    }
    float tl = (t0 + t1) + (t2 + t3);
#pragma unroll
    for (int n = 0; n < 20; ++n)
        g_h[(g * 20 + n) * H_DIM + c] = g_embT[at[n] * 128 + c] + tl;
}

// ---------------- tensor nodeside (layer 0 only), 4 graphs/block ----------
#define NS4A 0
#define NS4B 21760
#define NS4_TOT 91392

__global__ __launch_bounds__(256, 2) void k_nodeside_t4(int L)
{
    extern __shared__ char sm[];
    int gb = blockIdx.x, tid = threadIdx.x;
    int w = tid >> 5, lane = tid & 31;
    int gq = lane >> 2, tig = lane & 3;

    for (int idx = tid; idx < 5120; idx += 256) {
        int r = idx >> 6, c2 = idx & 63;
        const float* src = g_h + ((size_t)gb * 80 + r) * 128 + c2 * 2;
        *(u32*)(sm + NS4A + r * 272 + c2 * 4) = pack_h2(src[0], src[1]);
    }
    {
        const u32* src = (const u32*)(g_w1n + L * 32768);
        for (int idx = tid; idx < 16384; idx += 256) {
            int n = idx >> 6, k2 = idx & 63;
            *(u32*)(sm + NS4B + n * 272 + k2 * 4) = src[idx];
        }
    }
    __syncthreads();

    int njb = w * 4;
    float acc[5][4][4];
#pragma unroll
    for (int m = 0; m < 5; ++m)
#pragma unroll
        for (int j = 0; j < 4; ++j)
            acc[m][j][0] = acc[m][j][1] = acc[m][j][2] = acc[m][j][3] = 0.f;
#pragma unroll
    for (int ks = 0; ks < 8; ++ks) {
        int kc = ks * 16 + 2 * tig;
        u32 bh[4][2];
#pragma unroll
        for (int j = 0; j < 4; ++j) {
            const char* b = sm + NS4B + ((njb + j) * 8 + gq) * 272 + kc * 2;
            bh[j][0] = *(const u32*)b;
            bh[j][1] = *(const u32*)(b + 16);
        }
#pragma unroll
        for (int m = 0; m < 5; ++m) {
            u32 ah[4];
            const char* Ab = sm + NS4A + (m * 16) * 272;
            ah[0] = *(const u32*)(Ab + gq * 272 + kc * 2);
            ah[1] = *(const u32*)(Ab + (gq + 8) * 272 + kc * 2);
            ah[2] = *(const u32*)(Ab + gq * 272 + (kc + 8) * 2);
            ah[3] = *(const u32*)(Ab + (gq + 8) * 272 + (kc + 8) * 2);
#pragma unroll
            for (int j = 0; j < 4; ++j)
                mma_f16(acc[m][j], ah, bh[j][0], bh[j][1]);
        }
    }
#pragma unroll
    for (int m = 0; m < 5; ++m) {
        int rowA = m * 16 + gq, rowB = rowA + 8;
#pragma unroll
        for (int j = 0; j < 4; ++j) {
            int n = (njb + j) * 8 + 2 * tig;
            size_t baseA = ((size_t)gb * 80 + rowA) * 128;
            size_t baseB = ((size_t)gb * 80 + rowB) * 128;
            float* dA = (n < 128) ? (g_hs + baseA + n) : (g_hd + baseA + n - 128);
            float* dB = (n < 128) ? (g_hs + baseB + n) : (g_hd + baseB + n - 128);
            *(float2*)dA = make_float2(acc[m][j][0], acc[m][j][1]);
            *(float2*)dB = make_float2(acc[m][j][2], acc[m][j][3]);
        }
    }
}

// ---------------- persistent edge kernel: 26 warps, 1 tile/warp ----------
#define SW1 0           // 18432
#define SW2 18432       // -> 53248
#define SAW 53248       // 26 x 4352 -> 166400
#define SHS 166400      // 10240 -> 176640
#define SHD 176640      // -> 186880
#define SB2 186880      // -> 187392
#define SPART 187392    // 25600 -> 212992
#define SM_TOT 212992

__global__ __launch_bounds__(EW_THREADS, 1) void k_edge_s(
    int L, const float* __restrict__ eb2)
{
    extern __shared__ char sm[];
    int tid = threadIdx.x;
    int w = tid >> 5, lane = tid & 31;
    int gq = lane >> 2, tig = lane & 3;

    {
        const u32* src = (const u32*)(g_w1d + L * 8192);
        for (int idx = tid; idx < 4096; idx += EW_THREADS) {
            int n = idx >> 5, k2 = idx & 31;
            *(u32*)(sm + SW1 + n * 144 + k2 * 4) = src[idx];
        }
        const u32* src2 = (const u32*)(g_w2 + L * 16384);
        for (int idx = tid; idx < 8192; idx += EW_THREADS) {
            int n = idx >> 6, k2 = idx & 63;
            *(u32*)(sm + SW2 + n * 272 + k2 * 4) = src2[idx];
        }
        if (tid < 128) ((float*)(sm + SB2))[tid] = eb2[tid];
    }

    float* hs = (float*)(sm + SHS);
    float* hd = (float*)(sm + SHD);
    float* b2 = (float*)(sm + SB2);
    float* part = (float*)(sm + SPART);
    char* AB = sm + SAW + w * 4352;
    const float* lat4 = g_latterm + (size_t)L * G_CNT * H_DIM;

    for (int g0 = blockIdx.x; g0 < G_CNT; g0 += EDGE_GRID) {
        __syncthreads();
        for (int i = tid; i < 2560; i += EW_THREADS) {
            hs[i] = g_hs[(size_t)g0 * 2560 + i] + lat4[g0 * 128 + (i & 127)];
            hd[i] = g_hd[(size_t)g0 * 2560 + i];
        }
        __syncthreads();

        if (w < 25) {
            int e0 = w * 16;
            {
                const uint4* sH = (const uint4*)(g_disH + ((size_t)g0 * 400 + e0) * 64);
#pragma unroll
                for (int q = 0; q < 4; ++q) {
                    int idx = lane + q * 32;
                    int row = idx >> 3, seg = idx & 7;
                    *(uint4*)(AB + row * 144 + seg * 16) = sH[row * 8 + seg];
                }
            }
            __syncwarp();
            // preload GEMM1 A fragments (dis) -> regs so epA can overwrite AB
            u32 fr[4][4];
#pragma unroll
            for (int ks = 0; ks < 4; ++ks) {
                int kc = ks * 16 + 2 * tig;
                fr[ks][0] = *(const u32*)(AB + gq * 144 + kc * 2);
                fr[ks][1] = *(const u32*)(AB + (gq + 8) * 144 + kc * 2);
                fr[ks][2] = *(const u32*)(AB + gq * 144 + (kc + 8) * 2);
                fr[ks][3] = *(const u32*)(AB + (gq + 8) * 144 + (kc + 8) * 2);
            }
            __syncwarp();

            int eA = e0 + gq, eB = e0 + gq + 8;
            int srcA = eA / 20, dstA = eA - srcA * 20;
            int srcB = eB / 20, dstB = eB - srcB * 20;

            // ---- GEMM1 + epilogue A, two n-halves (32 live accs) ----
#pragma unroll
            for (int nh = 0; nh < 2; ++nh) {
                float acc[8][4];
#pragma unroll
                for (int j = 0; j < 8; ++j)
                    acc[j][0] = acc[j][1] = acc[j][2] = acc[j][3] = 0.f;
#pragma unroll
                for (int ks = 0; ks < 4; ++ks) {
                    int kc = ks * 16 + 2 * tig;
#pragma unroll
                    for (int j = 0; j < 8; ++j) {
                        const char* bh = sm + SW1 + (((nh * 8 + j) * 8 + gq) * 72 + kc) * 2;
                        mma_f16(acc[j], fr[ks], *(const u32*)bh, *(const u32*)(bh + 16));
                    }
                }
#pragma unroll
                for (int j = 0; j < 8; ++j) {
                    int c0 = (nh * 8 + j) * 8 + 2 * tig;
                    float2 hsA = *(const float2*)&hs[srcA * 128 + c0];
                    float2 hdA = *(const float2*)&hd[dstA * 128 + c0];
                    float2 hsB = *(const float2*)&hs[srcB * 128 + c0];
                    float2 hdB = *(const float2*)&hd[dstB * 128 + c0];
                    float x0 = siluf(acc[j][0] + hsA.x + hdA.x);
                    float x1 = siluf(acc[j][1] + hsA.y + hdA.y);
                    float x2 = siluf(acc[j][2] + hsB.x + hdB.x);
                    float x3 = siluf(acc[j][3] + hsB.y + hdB.y);
                    *(u32*)(AB + gq * 272 + c0 * 2) = pack_h2(x0, x1);
                    *(u32*)(AB + (gq + 8) * 272 + c0 * 2) = pack_h2(x2, x3);
                }
            }
            __syncwarp();

            // ---- GEMM2 + epilogue B (shuffle reduction), two n-halves ----
            int sA = e0 / 20;
            int bnd = 20 * (sA + 1) - e0;
            if (bnd > 16) bnd = 16;
            bool lo = gq < bnd, hi = (gq + 8) < bnd;
#pragma unroll
            for (int nh = 0; nh < 2; ++nh) {
                float acc2[8][4];
#pragma unroll
                for (int j = 0; j < 8; ++j)
                    acc2[j][0] = acc2[j][1] = acc2[j][2] = acc2[j][3] = 0.f;
#pragma unroll
                for (int ks = 0; ks < 8; ++ks) {
                    int kc = ks * 16 + 2 * tig;
                    u32 ah[4];
                    ah[0] = *(const u32*)(AB + gq * 272 + kc * 2);
                    ah[1] = *(const u32*)(AB + (gq + 8) * 272 + kc * 2);
                    ah[2] = *(const u32*)(AB + gq * 272 + (kc + 8) * 2);
                    ah[3] = *(const u32*)(AB + (gq + 8) * 272 + (kc + 8) * 2);
#pragma unroll
                    for (int j = 0; j < 8; ++j) {
                        const char* bh = sm + SW2 + (((nh * 8 + j) * 8 + gq) * 136 + kc) * 2;
                        mma_f16(acc2[j], ah, *(const u32*)bh, *(const u32*)(bh + 16));
                    }
                }
#pragma unroll
                for (int j = 0; j < 8; ++j) {
                    int c0 = (nh * 8 + j) * 8 + 2 * tig;
                    float2 bb = *(const float2*)&b2[c0];
                    float v0 = siluf(acc2[j][0] + bb.x);
                    float v1 = siluf(acc2[j][1] + bb.y);
                    float v2 = siluf(acc2[j][2] + bb.x);
                    float v3 = siluf(acc2[j][3] + bb.y);
                    float p0x = (lo ? v0 : 0.f) + (hi ? v2 : 0.f);
                    float p0y = (lo ? v1 : 0.f) + (hi ? v3 : 0.f);
                    float p1x = (lo ? 0.f : v0) + (hi ? 0.f : v2);
                    float p1y = (lo ? 0.f : v1) + (hi ? 0.f : v3);
#pragma unroll
                    for (int off = 4; off <= 16; off <<= 1) {
                        p0x += __shfl_xor_sync(0xFFFFFFFF, p0x, off);
                        p0y += __shfl_xor_sync(0xFFFFFFFF, p0y, off);
                        p1x += __shfl_xor_sync(0xFFFFFFFF, p1x, off);
                        p1y += __shfl_xor_sync(0xFFFFFFFF, p1y, off);
                    }
                    if (gq == 0) {
                        part[w * 256 + c0] = p0x;
                        part[w * 256 + c0 + 1] = p0y;
                        part[w * 256 + 128 + c0] = p1x;
                        part[w * 256 + 128 + c0 + 1] = p1y;
                    }
                }
            }
        }
        __syncthreads();

        for (int idx = tid; idx < 2560; idx += EW_THREADS) {
            int s = idx >> 7, c = idx & 127;
            int t0 = (20 * s) >> 4, t1 = (20 * s + 19) >> 4;
            float a = 0.f;
            for (int t = t0; t <= t1; ++t) {
                int sA2 = (16 * t) / 20;
                int sB2 = (16 * t + 15) / 20;
                if (sA2 == s) a += part[t * 256 + c];
                else if (sB2 == s) a += part[t * 256 + 128 + c];
            }
            g_agg[(size_t)g0 * 2560 + idx] = a * 0.05f;
        }
    }
}

// ---------------- fused node MLP + next-layer nodeside, 8 graphs/block ----
#define M8A1 0
#define M8B1 84480
#define M8A2 0
#define M8B2 43520
#define M8WN 78336
#define M8_TOT 152064

__global__ __launch_bounds__(256, 1) void k_nodemlp_f(
    int L, int has_next,
    const float* __restrict__ nb1, const float* __restrict__ nb2)
{
    extern __shared__ char sm[];
    int gb = blockIdx.x, tid = threadIdx.x;
    int w = tid >> 5, lane = tid & 31;
    int gq = lane >> 2, tig = lane & 3;

    for (int idx = tid; idx < 20480; idx += 256) {
        int r = idx >> 7, c2 = idx & 127;
        float a0, a1;
        size_t base = ((size_t)gb * 160 + r) * 128;
        if (c2 < 64) {
            const float* s = g_h + base + c2 * 2;
            a0 = s[0]; a1 = s[1];
        } else {
            const float* s = g_agg + base + (c2 - 64) * 2;
            a0 = s[0]; a1 = s[1];
        }
        *(u32*)(sm + M8A1 + r * 528 + c2 * 4) = pack_h2(a0, a1);
    }
    {
        const u32* src = (const u32*)(g_nw1 + L * 32768);
        for (int idx = tid; idx < 16384; idx += 256) {
            int n = idx >> 7, k2 = idx & 127;
            *(u32*)(sm + M8B1 + n * 528 + k2 * 4) = src[idx];
        }
    }
    __syncthreads();

    int njb = w * 2;
    float acc[10][2][4];
#pragma unroll
    for (int m = 0; m < 10; ++m)
#pragma unroll
        for (int j = 0; j < 2; ++j)
            acc[m][j][0] = acc[m][j][1] = acc[m][j][2] = acc[m][j][3] = 0.f;
#pragma unroll
    for (int ks = 0; ks < 16; ++ks) {
        int kc = ks * 16 + 2 * tig;
        u32 bh[2][2];
#pragma unroll
        for (int j = 0; j < 2; ++j) {
            const char* b = sm + M8B1 + ((njb + j) * 8 + gq) * 528 + kc * 2;
            bh[j][0] = *(const u32*)b;
            bh[j][1] = *(const u32*)(b + 16);
        }
#pragma unroll
        for (int m = 0; m < 10; ++m) {
            u32 ah[4];
            const char* Ab = sm + M8A1 + (m * 16) * 528;
            ah[0] = *(const u32*)(Ab + gq * 528 + kc * 2);
            ah[1] = *(const u32*)(Ab + (gq + 8) * 528 + kc * 2);
            ah[2] = *(const u32*)(Ab + gq * 528 + (kc + 8) * 2);
            ah[3] = *(const u32*)(Ab + (gq + 8) * 528 + (kc + 8) * 2);
#pragma unroll
            for (int j = 0; j < 2; ++j)
                mma_f16(acc[m][j], ah, bh[j][0], bh[j][1]);
        }
    }
    __syncthreads();

#pragma unroll
    for (int m = 0; m < 10; ++m) {
        int rA = m * 16 + gq;
#pragma unroll
        for (int j = 0; j < 2; ++j) {
            int c0 = (njb + j) * 8 + 2 * tig;
            float bb0 = __ldg(nb1 + c0), bb1 = __ldg(nb1 + c0 + 1);
            *(u32*)(sm + M8A2 + rA * 272 + c0 * 2) =
                pack_h2(siluf(acc[m][j][0] + bb0), siluf(acc[m][j][1] + bb1));
            *(u32*)(sm + M8A2 + (rA + 8) * 272 + c0 * 2) =
                pack_h2(siluf(acc[m][j][2] + bb0), siluf(acc[m][j][3] + bb1));
        }
    }
    {
        const u32* src2 = (const u32*)(g_nw2 + L * 16384);
        for (int idx = tid; idx < 8192; idx += 256) {
            int n = idx >> 6, k2 = idx & 63;
            *(u32*)(sm + M8B2 + n * 272 + k2 * 4) = src2[idx];
        }
        if (has_next) {
            const u32* srcW = (const u32*)(g_w1n + (L + 1) * 32768);
            for (int idx = tid; idx < 16384; idx += 256) {
                int n = idx >> 6, k2 = idx & 63;
                *(u32*)(sm + M8WN + n * 272 + k2 * 4) = srcW[idx];
            }
        }
    }
    __syncthreads();

    float acc2[10][2][4];
#pragma unroll
    for (int m = 0; m < 10; ++m)
#pragma unroll
        for (int j = 0; j < 2; ++j)
            acc2[m][j][0] = acc2[m][j][1] = acc2[m][j][2] = acc2[m][j][3] = 0.f;
#pragma unroll
    for (int ks = 0; ks < 8; ++ks) {
        int kc = ks * 16 + 2 * tig;
        u32 bh[2][2];
#pragma unroll
        for (int j = 0; j < 2; ++j) {
            const char* b = sm + M8B2 + ((njb + j) * 8 + gq) * 272 + kc * 2;
            bh[j][0] = *(const u32*)b;
            bh[j][1] = *(const u32*)(b + 16);
        }
#pragma unroll
        for (int m = 0; m < 10; ++m) {
            u32 ah[4];
            const char* Ab = sm + M8A2 + (m * 16) * 272;
            ah[0] = *(const u32*)(Ab + gq * 272 + kc * 2);
            ah[1] = *(const u32*)(Ab + (gq + 8) * 272 + kc * 2);
            ah[2] = *(const u32*)(Ab + gq * 272 + (kc + 8) * 2);
            ah[3] = *(const u32*)(Ab + (gq + 8) * 272 + (kc + 8) * 2);
#pragma unroll
            for (int j = 0; j < 2; ++j)
                mma_f16(acc2[m][j], ah, bh[j][0], bh[j][1]);
        }
    }
    __syncthreads();

#pragma unroll
    for (int m = 0; m < 10; ++m) {
        int rA = m * 16 + gq, rB = rA + 8;
#pragma unroll
        for (int j = 0; j < 2; ++j) {
            int c0 = (njb + j) * 8 + 2 * tig;
            float bb0 = __ldg(nb2 + c0), bb1 = __ldg(nb2 + c0 + 1);
            {
                float* d = g_h + ((size_t)gb * 160 + rA) * 128 + c0;
                float2 o = *(float2*)d;
                o.x += siluf(acc2[m][j][0] + bb0);
                o.y += siluf(acc2[m][j][1] + bb1);
                *(float2*)d = o;
                if (has_next)
                    *(u32*)(sm + M8A2 + rA * 272 + c0 * 2) = pack_h2(o.x, o.y);
            }
            {
                float* d = g_h + ((size_t)gb * 160 + rB) * 128 + c0;
                float2 o = *(float2*)d;
                o.x += siluf(acc2[m][j][2] + bb0);
                o.y += siluf(acc2[m][j][3] + bb1);
                *(float2*)d = o;
                if (has_next)
                    *(u32*)(sm + M8A2 + rB * 272 + c0 * 2) = pack_h2(o.x, o.y);
            }
        }
    }
    if (!has_next) return;
    __syncthreads();

    int nj3 = w * 4;
#pragma unroll
    for (int mh = 0; mh < 2; ++mh) {
        float acc3[5][4][4];
#pragma unroll
        for (int m = 0; m < 5; ++m)
#pragma unroll
            for (int j = 0; j < 4; ++j)
                acc3[m][j][0] = acc3[m][j][1] = acc3[m][j][2] = acc3[m][j][3] = 0.f;
#pragma unroll
        for (int ks = 0; ks < 8; ++ks) {
            int kc = ks * 16 + 2 * tig;
            u32 bh[4][2];
#pragma unroll
            for (int j = 0; j < 4; ++j) {
                const char* b = sm + M8WN + ((nj3 + j) * 8 + gq) * 272 + kc * 2;
                bh[j][0] = *(const u32*)b;
                bh[j][1] = *(const u32*)(b + 16);
            }
#pragma unroll
            for (int m = 0; m < 5; ++m) {
                u32 ah[4];
                const char* Ab = sm + M8A2 + ((mh * 5 + m) * 16) * 272;
                ah[0] = *(const u32*)(Ab + gq * 272 + kc * 2);
                ah[1] = *(const u32*)(Ab + (gq + 8) * 272 + kc * 2);
                ah[2] = *(const u32*)(Ab + gq * 272 + (kc + 8) * 2);
                ah[3] = *(const u32*)(Ab + (gq + 8) * 272 + (kc + 8) * 2);
#pragma unroll
                for (int j = 0; j < 4; ++j)
                    mma_f16(acc3[m][j], ah, bh[j][0], bh[j][1]);
            }
        }
#pragma unroll
        for (int m = 0; m < 5; ++m) {
            int rowA = (mh * 5 + m) * 16 + gq, rowB = rowA + 8;
#pragma unroll
            for (int j = 0; j < 4; ++j) {
                int n = (nj3 + j) * 8 + 2 * tig;
                size_t baseA = ((size_t)gb * 160 + rowA) * 128;
                size_t baseB = ((size_t)gb * 160 + rowB) * 128;
                float* dA = (n < 128) ? (g_hs + baseA + n) : (g_hd + baseA + n - 128);
                float* dB = (n < 128) ? (g_hs + baseB + n) : (g_hd + baseB + n - 128);
                *(float2*)dA = make_float2(acc3[m][j][0], acc3[m][j][1]);
                *(float2*)dB = make_float2(acc3[m][j][2], acc3[m][j][3]);
            }
        }
    }
}

// ---------------- output heads ----------------
__global__ __launch_bounds__(128) void k_final(
    const float* __restrict__ lattices, const float* __restrict__ coord_w,
    const float* __restrict__ lattice_w, float* __restrict__ out)
{
    __shared__ __align__(16) float hT[128 * 20];
    __shared__ float gf[128];
    __shared__ float pre[9];
    int g = blockIdx.x, tid = threadIdx.x;
    for (int n = 0; n < 20; ++n)
        hT[tid * 20 + n] = g_h[(g * 20 + n) * H_DIM + tid];
    __syncthreads();
    float s = 0.f;
#pragma unroll
    for (int n = 0; n < 20; ++n) s += hT[tid * 20 + n];
    gf[tid] = s * 0.05f;
    __syncthreads();
    if (tid < 9) {
        float acc = 0.f;
        for (int k = 0; k < 128; ++k) acc += gf[k] * lattice_w[k * 9 + tid];
        pre[tid] = acc;
    }
    __syncthreads();
    if (tid < 9) {
        int i = tid / 3, kk = tid % 3;
        float v = 0.f;
#pragma unroll
        for (int j = 0; j < 3; ++j)
            v += pre[i * 3 + j] * lattices[g * 9 + j * 3 + kk];
        out[g * 9 + tid] = v;
    }
    if (tid < 60) {
        int n = tid / 3, c = tid % 3;
        float acc = 0.f;
        for (int k = 0; k < 128; ++k) acc += hT[k * 20 + n] * coord_w[k * 3 + c];
        out[G_CNT * 9 + (g * 20 + n) * 3 + c] = acc;
    }
}

// ---------------- launch ----------------
extern "C" void kernel_launch(void* const* d_in, const int* in_sizes, int n_in,
                              void* d_out, int out_size) {
    const int*   atom_types = (const int*)d_in[0];
    const float* frac       = (const float*)d_in[1];
    const float* lattices   = (const float*)d_in[2];
    const float* t          = (const float*)d_in[3];
    const float* emb_table  = (const float*)d_in[7];
    const float* w_latent   = (const float*)d_in[8];
    const float* b_latent   = (const float*)d_in[9];
    const float* ew1        = (const float*)d_in[10];
    const float* eb1        = (const float*)d_in[11];
    const float* ew2        = (const float*)d_in[12];
    const float* eb2        = (const float*)d_in[13];
    const float* nw1        = (const float*)d_in[14];
    const float* nb1        = (const float*)d_in[15];
    const float* nw2        = (const float*)d_in[16];
    const float* nb2        = (const float*)d_in[17];
    const float* coord_w    = (const float*)d_in[18];
    const float* lattice_w  = (const float*)d_in[19];
    float* out = (float*)d_out;

    cudaFuncSetAttribute(k_edge_s, cudaFuncAttributeMaxDynamicSharedMemorySize, SM_TOT);
    cudaFuncSetAttribute(k_nodemlp_f, cudaFuncAttributeMaxDynamicSharedMemorySize, M8_TOT);
    cudaFuncSetAttribute(k_nodeside_t4, cudaFuncAttributeMaxDynamicSharedMemorySize, NS4_TOT);

    k_prep<<<(NLAYER * 106496 + 255) / 256, 256>>>(ew1, ew2, nw1, nw2);
    k_prep_emb<<<100, 128>>>(emb_table, w_latent);
    k_latip<<<G_CNT, 32>>>(lattices);
    k_latall<<<NLAYER * G_CNT * 128 / 256, 256>>>(ew1, eb1);
    k_embed<<<G_CNT, 128>>>(atom_types, t, w_latent, b_latent);
    k_dis<<<E_CNT / 128, 128>>>(frac);
    k_nodeside_t4<<<G_CNT / 4, 256, NS4_TOT>>>(0);
    for (int i = 0; i < NLAYER; ++i) {
        k_edge_s<<<EDGE_GRID, EW_THREADS, SM_TOT>>>(i, eb2 + i * 128);
        k_nodemlp_f<<<G_CNT / 8, 256, M8_TOT>>>(i, (i < NLAYER - 1) ? 1 : 0,
                                                nb1 + i * 128, nb2 + i * 128);
    }
    k_final<<<G_CNT, 128>>>(lattices, coord_w, lattice_w, out);
}

// round 15
// speedup vs baseline: 1.2559x; 1.0513x over previous
#include <cuda_runtime.h>
#include <cuda_bf16.h>
#include <cuda_fp16.h>
#include <math.h>
#include <stdint.h>

#define G_CNT 1024
#define A_CNT 20
#define N_CNT (G_CNT * A_CNT)
#define E_CNT (G_CNT * A_CNT * A_CNT)
#define H_DIM 128
#define NLAYER 4
#define EDGE_GRID 148
#define EW_THREADS 832

typedef unsigned long long u64;
typedef unsigned int u32;
typedef unsigned short u16;

// ---------------- scratch ----------------
__device__ float g_h[N_CNT * H_DIM];
__device__ float g_hs[N_CNT * H_DIM];
__device__ float g_hd[N_CNT * H_DIM];
__device__ float g_agg[N_CNT * H_DIM];
__device__ float g_latip[G_CNT * 9];
__device__ float g_latterm[NLAYER * G_CNT * H_DIM];
__device__ float g_embT[100 * H_DIM];
__device__ u16 g_disH[(size_t)E_CNT * 64];
__device__ u16 g_w1d[NLAYER * 128 * 64];
__device__ u16 g_w1n[NLAYER * 256 * 128];
__device__ u16 g_w2[NLAYER * 128 * 128];
__device__ u16 g_nw1[NLAYER * 128 * 256];
__device__ u16 g_nw2[NLAYER * 128 * 128];

__device__ __forceinline__ float siluf(float x) {
    return __fdividef(x, 1.0f + __expf(-x));
}
__device__ __forceinline__ u16 h_rn(float x) {
    return __half_as_ushort(__float2half_rn(x));
}
__device__ __forceinline__ u32 pack_h2(float a, float b) {
    __half2 hh = __floats2half2_rn(a, b);
    return *(u32*)&hh;
}
__device__ __forceinline__ void mma_f16(float c[4], const u32 a[4], u32 b0, u32 b1) {
    asm volatile(
        "mma.sync.aligned.m16n8k16.row.col.f32.f16.f16.f32 "
        "{%0,%1,%2,%3}, {%4,%5,%6,%7}, {%8,%9}, {%0,%1,%2,%3};"
        : "+f"(c[0]), "+f"(c[1]), "+f"(c[2]), "+f"(c[3])
        : "r"(a[0]), "r"(a[1]), "r"(a[2]), "r"(a[3]), "r"(b0), "r"(b1));
}

// ---------------- weight prep ----------------
__global__ __launch_bounds__(256) void k_prep(
    const float* __restrict__ ew1, const float* __restrict__ ew2,
    const float* __restrict__ nw1, const float* __restrict__ nw2)
{
    int i = blockIdx.x * 256 + threadIdx.x;
    if (i >= NLAYER * 106496) return;
    int L = i / 106496, j = i % 106496;
    const float* e1 = ew1 + L * 325 * 128;
    const float* e2 = ew2 + L * 128 * 128;
    const float* n1 = nw1 + L * 256 * 128;
    const float* n2 = nw2 + L * 128 * 128;
    if (j < 8192) {
        int n = j >> 6, k = j & 63;
        float v = (k < 60) ? e1[(265 + k) * 128 + n] : 0.f;
        g_w1d[L * 8192 + j] = h_rn(v);
    } else if (j < 40960) {
        int jj = j - 8192;
        int n = jj >> 7, k = jj & 127;
        float v = (n < 128) ? e1[k * 128 + n] : e1[(128 + k) * 128 + (n - 128)];
        g_w1n[L * 32768 + jj] = h_rn(v);
    } else if (j < 57344) {
        int jj = j - 40960;
        int n = jj >> 7, k = jj & 127;
        g_w2[L * 16384 + jj] = h_rn(e2[k * 128 + n]);
    } else if (j < 90112) {
        int jj = j - 57344;
        int n = jj >> 8, k = jj & 255;
        g_nw1[L * 32768 + jj] = h_rn(n1[k * 128 + n]);
    } else {
        int jj = j - 90112;
        int n = jj >> 7, k = jj & 127;
        g_nw2[L * 16384 + jj] = h_rn(n2[k * 128 + n]);
    }
}

__global__ __launch_bounds__(128) void k_prep_emb(
    const float* __restrict__ emb_table, const float* __restrict__ w_latent)
{
    int a = blockIdx.x, c = threadIdx.x;
    float s = 0.f;
#pragma unroll 4
    for (int k = 0; k < 128; ++k)
        s = fmaf(emb_table[a * 128 + k], w_latent[k * 128 + c], s);
    g_embT[a * 128 + c] = s;
}

__global__ void k_latip(const float* __restrict__ lattices) {
    int g = blockIdx.x, tid = threadIdx.x;
    if (tid < 9) {
        int i = tid / 3, k = tid % 3;
        float s = 0.f;
#pragma unroll
        for (int j = 0; j < 3; ++j)
            s += lattices[g * 9 + i * 3 + j] * lattices[g * 9 + k * 3 + j];
        g_latip[g * 9 + tid] = s;
    }
}

__global__ __launch_bounds__(256) void k_latall(
    const float* __restrict__ ew1, const float* __restrict__ eb1)
{
    int idx = blockIdx.x * 256 + threadIdx.x;
    int L = idx >> 17;
    int g = (idx >> 7) & (G_CNT - 1);
    int c = idx & 127;
    float lt = eb1[L * 128 + c];
#pragma unroll
    for (int j = 0; j < 9; ++j)
        lt += g_latip[g * 9 + j] * ew1[L * 325 * 128 + (256 + j) * 128 + c];
    g_latterm[idx] = lt;
}

__global__ __launch_bounds__(128) void k_dis(const float* __restrict__ fc) {
    __shared__ u32 hiS[128 * 33];
    int tid = threadIdx.x;
    size_t e0 = (size_t)blockIdx.x * 128;
    int e = (int)e0 + tid;
    int g = e / 400, r = e % 400;
    int src = g * 20 + r / 20;
    int dst = g * 20 + r % 20;
    u16* hrow = (u16*)(hiS + tid * 33);
#pragma unroll
    for (int c = 0; c < 3; ++c) {
        float d = fc[dst * 3 + c] - fc[src * 3 + c];
        d -= floorf(d);
        float s1, c1;
        sincospif(2.0f * d, &s1, &c1);
        float s = 0.f, co = 1.f;
        hrow[c * 10] = 0;
        hrow[30 + c * 10] = h_rn(1.f);
#pragma unroll
        for (int f = 1; f < 10; ++f) {
            float ns = s * c1 + co * s1;
            float nc = co * c1 - s * s1;
            s = ns; co = nc;
            hrow[c * 10 + f] = h_rn(s);
            hrow[30 + c * 10 + f] = h_rn(co);
        }
    }
#pragma unroll
    for (int k = 60; k < 64; ++k) hrow[k] = 0;
    __syncthreads();
    u32* gh = (u32*)g_disH + e0 * 32;
    for (int i = tid; i < 4096; i += 128)
        gh[i] = hiS[(i >> 5) * 33 + (i & 31)];
}

__global__ __launch_bounds__(128) void k_embed(
    const int* __restrict__ atom_types, const float* __restrict__ t,
    const float* __restrict__ w_latent, const float* __restrict__ b_latent)
{
    __shared__ int at[20];
    __shared__ float ts[256];
    int g = blockIdx.x, c = threadIdx.x;
    if (c < 20) at[c] = atom_types[g * 20 + c];
    ts[c] = t[g * 256 + c];
    ts[c + 128] = t[g * 256 + c + 128];
    __syncthreads();
    float t0 = b_latent[c], t1 = 0.f, t2 = 0.f, t3 = 0.f;
#pragma unroll 8
    for (int k = 0; k < 256; k += 4) {
        t0 = fmaf(ts[k],     w_latent[(128 + k) * 128 + c], t0);
        t1 = fmaf(ts[k + 1], w_latent[(129 + k) * 128 + c], t1);
        t2 = fmaf(ts[k + 2], w_latent[(130 + k) * 128 + c], t2);
        t3 = fmaf(ts[k + 3], w_latent[(131 + k) * 128 + c], t3);
    }
    float tl = (t0 + t1) + (t2 + t3);
#pragma unroll
    for (int n = 0; n < 20; ++n)
        g_h[(g * 20 + n) * H_DIM + c] = g_embT[at[n] * 128 + c] + tl;
}

// ---------------- tensor nodeside (layer 0 only), 4 graphs/block ----------
#define NS4A 0
#define NS4B 21760
#define NS4_TOT 91392

__global__ __launch_bounds__(256, 2) void k_nodeside_t4(int L)
{
    extern __shared__ char sm[];
    int gb = blockIdx.x, tid = threadIdx.x;
    int w = tid >> 5, lane = tid & 31;
    int gq = lane >> 2, tig = lane & 3;

    for (int idx = tid; idx < 5120; idx += 256) {
        int r = idx >> 6, c2 = idx & 63;
        const float* src = g_h + ((size_t)gb * 80 + r) * 128 + c2 * 2;
        *(u32*)(sm + NS4A + r * 272 + c2 * 4) = pack_h2(src[0], src[1]);
    }
    {
        const u32* src = (const u32*)(g_w1n + L * 32768);
        for (int idx = tid; idx < 16384; idx += 256) {
            int n = idx >> 6, k2 = idx & 63;
            *(u32*)(sm + NS4B + n * 272 + k2 * 4) = src[idx];
        }
    }
    __syncthreads();

    int njb = w * 4;
    float acc[5][4][4];
#pragma unroll
    for (int m = 0; m < 5; ++m)
#pragma unroll
        for (int j = 0; j < 4; ++j)
            acc[m][j][0] = acc[m][j][1] = acc[m][j][2] = acc[m][j][3] = 0.f;
#pragma unroll
    for (int ks = 0; ks < 8; ++ks) {
        int kc = ks * 16 + 2 * tig;
        u32 bh[4][2];
#pragma unroll
        for (int j = 0; j < 4; ++j) {
            const char* b = sm + NS4B + ((njb + j) * 8 + gq) * 272 + kc * 2;
            bh[j][0] = *(const u32*)b;
            bh[j][1] = *(const u32*)(b + 16);
        }
#pragma unroll
        for (int m = 0; m < 5; ++m) {
            u32 ah[4];
            const char* Ab = sm + NS4A + (m * 16) * 272;
            ah[0] = *(const u32*)(Ab + gq * 272 + kc * 2);
            ah[1] = *(const u32*)(Ab + (gq + 8) * 272 + kc * 2);
            ah[2] = *(const u32*)(Ab + gq * 272 + (kc + 8) * 2);
            ah[3] = *(const u32*)(Ab + (gq + 8) * 272 + (kc + 8) * 2);
#pragma unroll
            for (int j = 0; j < 4; ++j)
                mma_f16(acc[m][j], ah, bh[j][0], bh[j][1]);
        }
    }
#pragma unroll
    for (int m = 0; m < 5; ++m) {
        int rowA = m * 16 + gq, rowB = rowA + 8;
#pragma unroll
        for (int j = 0; j < 4; ++j) {
            int n = (njb + j) * 8 + 2 * tig;
            size_t baseA = ((size_t)gb * 80 + rowA) * 128;
            size_t baseB = ((size_t)gb * 80 + rowB) * 128;
            float* dA = (n < 128) ? (g_hs + baseA + n) : (g_hd + baseA + n - 128);
            float* dB = (n < 128) ? (g_hs + baseB + n) : (g_hd + baseB + n - 128);
            *(float2*)dA = make_float2(acc[m][j][0], acc[m][j][1]);
            *(float2*)dB = make_float2(acc[m][j][2], acc[m][j][3]);
        }
    }
}

// ---------------- persistent edge kernel: 26 warps, 1 tile/warp,
//                  warp 25 prefetches next graph's hs/hd (double-buffered) --
#define SW1 0           // 18432
#define SW2 18432       // -> 53248
#define SAW 53248       // 25 x 4352 -> 162048
#define SHS0 162048     // 10240 -> 172288
#define SHD0 172288     // -> 182528
#define SHS1 182528     // -> 192768
#define SHD1 192768     // -> 203008
#define SB2 203008      // -> 203520
#define SPART 203520    // 25600 -> 229120
#define SM_TOT 229120

__global__ __launch_bounds__(EW_THREADS, 1) void k_edge_s(
    int L, const float* __restrict__ eb2)
{
    extern __shared__ char sm[];
    int tid = threadIdx.x;
    int w = tid >> 5, lane = tid & 31;
    int gq = lane >> 2, tig = lane & 3;

    {
        const u32* src = (const u32*)(g_w1d + L * 8192);
        for (int idx = tid; idx < 4096; idx += EW_THREADS) {
            int n = idx >> 5, k2 = idx & 31;
            *(u32*)(sm + SW1 + n * 144 + k2 * 4) = src[idx];
        }
        const u32* src2 = (const u32*)(g_w2 + L * 16384);
        for (int idx = tid; idx < 8192; idx += EW_THREADS) {
            int n = idx >> 6, k2 = idx & 63;
            *(u32*)(sm + SW2 + n * 272 + k2 * 4) = src2[idx];
        }
        if (tid < 128) ((float*)(sm + SB2))[tid] = eb2[tid];
    }

    float* b2 = (float*)(sm + SB2);
    float* part = (float*)(sm + SPART);
    char* AB = sm + SAW + w * 4352;   // valid for w < 25 only
    const float* lat4 = g_latterm + (size_t)L * G_CNT * H_DIM;

    // stage first graph into buffer 0 (all threads)
    {
        int g0 = blockIdx.x;
        float* hs0 = (float*)(sm + SHS0);
        float* hd0 = (float*)(sm + SHD0);
        for (int i = tid; i < 2560; i += EW_THREADS) {
            hs0[i] = g_hs[(size_t)g0 * 2560 + i] + lat4[g0 * 128 + (i & 127)];
            hd0[i] = g_hd[(size_t)g0 * 2560 + i];
        }
    }
    __syncthreads();

    int pp = 0;
    for (int g0 = blockIdx.x; g0 < G_CNT; g0 += EDGE_GRID, pp ^= 1) {
        float* hs = (float*)(sm + (pp ? SHS1 : SHS0));
        float* hd = (float*)(sm + (pp ? SHD1 : SHD0));

        if (w < 25) {
            int e0 = w * 16;
            {
                const uint4* sH = (const uint4*)(g_disH + ((size_t)g0 * 400 + e0) * 64);
#pragma unroll
                for (int q = 0; q < 4; ++q) {
                    int idx = lane + q * 32;
                    int row = idx >> 3, seg = idx & 7;
                    *(uint4*)(AB + row * 144 + seg * 16) = sH[row * 8 + seg];
                }
            }
            __syncwarp();
            u32 fr[4][4];
#pragma unroll
            for (int ks = 0; ks < 4; ++ks) {
                int kc = ks * 16 + 2 * tig;
                fr[ks][0] = *(const u32*)(AB + gq * 144 + kc * 2);
                fr[ks][1] = *(const u32*)(AB + (gq + 8) * 144 + kc * 2);
                fr[ks][2] = *(const u32*)(AB + gq * 144 + (kc + 8) * 2);
                fr[ks][3] = *(const u32*)(AB + (gq + 8) * 144 + (kc + 8) * 2);
            }
            __syncwarp();

            int eA = e0 + gq, eB = e0 + gq + 8;
            int srcA = eA / 20, dstA = eA - srcA * 20;
            int srcB = eB / 20, dstB = eB - srcB * 20;

            // ---- GEMM1 + epilogue A, two n-halves ----
#pragma unroll
            for (int nh = 0; nh < 2; ++nh) {
                float acc[8][4];
#pragma unroll
                for (int j = 0; j < 8; ++j)
                    acc[j][0] = acc[j][1] = acc[j][2] = acc[j][3] = 0.f;
#pragma unroll
                for (int ks = 0; ks < 4; ++ks) {
                    int kc = ks * 16 + 2 * tig;
#pragma unroll
                    for (int j = 0; j < 8; ++j) {
                        const char* bh = sm + SW1 + (((nh * 8 + j) * 8 + gq) * 72 + kc) * 2;
                        mma_f16(acc[j], fr[ks], *(const u32*)bh, *(const u32*)(bh + 16));
                    }
                }
#pragma unroll
                for (int j = 0; j < 8; ++j) {
                    int c0 = (nh * 8 + j) * 8 + 2 * tig;
                    float2 hsA = *(const float2*)&hs[srcA * 128 + c0];
                    float2 hdA = *(const float2*)&hd[dstA * 128 + c0];
                    float2 hsB = *(const float2*)&hs[srcB * 128 + c0];
                    float2 hdB = *(const float2*)&hd[dstB * 128 + c0];
                    float x0 = siluf(acc[j][0] + hsA.x + hdA.x);
                    float x1 = siluf(acc[j][1] + hsA.y + hdA.y);
                    float x2 = siluf(acc[j][2] + hsB.x + hdB.x);
                    float x3 = siluf(acc[j][3] + hsB.y + hdB.y);
                    *(u32*)(AB + gq * 272 + c0 * 2) = pack_h2(x0, x1);
                    *(u32*)(AB + (gq + 8) * 272 + c0 * 2) = pack_h2(x2, x3);
                }
            }
            __syncwarp();

            // ---- GEMM2 + epilogue B (shuffle reduction), two n-halves ----
            int sA = e0 / 20;
            int bnd = 20 * (sA + 1) - e0;
            if (bnd > 16) bnd = 16;
            bool lo = gq < bnd, hi = (gq + 8) < bnd;
#pragma unroll
            for (int nh = 0; nh < 2; ++nh) {
                float acc2[8][4];
#pragma unroll
                for (int j = 0; j < 8; ++j)
                    acc2[j][0] = acc2[j][1] = acc2[j][2] = acc2[j][3] = 0.f;
#pragma unroll
                for (int ks = 0; ks < 8; ++ks) {
                    int kc = ks * 16 + 2 * tig;
                    u32 ah[4];
                    ah[0] = *(const u32*)(AB + gq * 272 + kc * 2);
                    ah[1] = *(const u32*)(AB + (gq + 8) * 272 + kc * 2);
                    ah[2] = *(const u32*)(AB + gq * 272 + (kc + 8) * 2);
                    ah[3] = *(const u32*)(AB + (gq + 8) * 272 + (kc + 8) * 2);
#pragma unroll
                    for (int j = 0; j < 8; ++j) {
                        const char* bh = sm + SW2 + (((nh * 8 + j) * 8 + gq) * 136 + kc) * 2;
                        mma_f16(acc2[j], ah, *(const u32*)bh, *(const u32*)(bh + 16));
                    }
                }
#pragma unroll
                for (int j = 0; j < 8; ++j) {
                    int c0 = (nh * 8 + j) * 8 + 2 * tig;
                    float2 bb = *(const float2*)&b2[c0];
                    float v0 = siluf(acc2[j][0] + bb.x);
                    float v1 = siluf(acc2[j][1] + bb.y);
                    float v2 = siluf(acc2[j][2] + bb.x);
                    float v3 = siluf(acc2[j][3] + bb.y);
                    float p0x = (lo ? v0 : 0.f) + (hi ? v2 : 0.f);
                    float p0y = (lo ? v1 : 0.f) + (hi ? v3 : 0.f);
                    float p1x = (lo ? 0.f : v0) + (hi ? 0.f : v2);
                    float p1y = (lo ? 0.f : v1) + (hi ? 0.f : v3);
#pragma unroll
                    for (int off = 4; off <= 16; off <<= 1) {
                        p0x += __shfl_xor_sync(0xFFFFFFFF, p0x, off);
                        p0y += __shfl_xor_sync(0xFFFFFFFF, p0y, off);
                        p1x += __shfl_xor_sync(0xFFFFFFFF, p1x, off);
                        p1y += __shfl_xor_sync(0xFFFFFFFF, p1y, off);
                    }
                    if (gq == 0) {
                        part[w * 256 + c0] = p0x;
                        part[w * 256 + c0 + 1] = p0y;
                        part[w * 256 + 128 + c0] = p1x;
                        part[w * 256 + 128 + c0 + 1] = p1y;
                    }
                }
            }
        } else {
            // warp 25: prefetch next graph's hs(+lat)/hd into alternate buffer
            int gn = g0 + EDGE_GRID;
            if (gn < G_CNT) {
                float* hsn = (float*)(sm + (pp ? SHS0 : SHS1));
                float* hdn = (float*)(sm + (pp ? SHD0 : SHD1));
                for (int i = lane; i < 2560; i += 32) {
                    hsn[i] = g_hs[(size_t)gn * 2560 + i] + lat4[gn * 128 + (i & 127)];
                    hdn[i] = g_hd[(size_t)gn * 2560 + i];
                }
            }
        }
        __syncthreads();   // tiles done (part written), prefetch done

        for (int idx = tid; idx < 2560; idx += EW_THREADS) {
            int s = idx >> 7, c = idx & 127;
            int t0 = (20 * s) >> 4, t1 = (20 * s + 19) >> 4;
            float a = 0.f;
            for (int t = t0; t <= t1; ++t) {
                int sA2 = (16 * t) / 20;
                int sB2 = (16 * t + 15) / 20;
                if (sA2 == s) a += part[t * 256 + c];
                else if (sB2 == s) a += part[t * 256 + 128 + c];
            }
            g_agg[(size_t)g0 * 2560 + idx] = a * 0.05f;
        }
        __syncthreads();   // part consumed before next iteration overwrites
    }
}

// ---------------- fused node MLP + next-layer nodeside, 8 graphs/block ----
#define M8A1 0
#define M8B1 84480
#define M8A2 0
#define M8B2 43520
#define M8WN 78336
#define M8_TOT 152064

__global__ __launch_bounds__(256, 1) void k_nodemlp_f(
    int L, int has_next,
    const float* __restrict__ nb1, const float* __restrict__ nb2)
{
    extern __shared__ char sm[];
    int gb = blockIdx.x, tid = threadIdx.x;
    int w = tid >> 5, lane = tid & 31;
    int gq = lane >> 2, tig = lane & 3;

    for (int idx = tid; idx < 20480; idx += 256) {
        int r = idx >> 7, c2 = idx & 127;
        float a0, a1;
        size_t base = ((size_t)gb * 160 + r) * 128;
        if (c2 < 64) {
            const float* s = g_h + base + c2 * 2;
            a0 = s[0]; a1 = s[1];
        } else {
            const float* s = g_agg + base + (c2 - 64) * 2;
            a0 = s[0]; a1 = s[1];
        }
        *(u32*)(sm + M8A1 + r * 528 + c2 * 4) = pack_h2(a0, a1);
    }
    {
        const u32* src = (const u32*)(g_nw1 + L * 32768);
        for (int idx = tid; idx < 16384; idx += 256) {
            int n = idx >> 7, k2 = idx & 127;
            *(u32*)(sm + M8B1 + n * 528 + k2 * 4) = src[idx];
        }
    }
    __syncthreads();

    int njb = w * 2;
    float acc[10][2][4];
#pragma unroll
    for (int m = 0; m < 10; ++m)
#pragma unroll
        for (int j = 0; j < 2; ++j)
            acc[m][j][0] = acc[m][j][1] = acc[m][j][2] = acc[m][j][3] = 0.f;
#pragma unroll
    for (int ks = 0; ks < 16; ++ks) {
        int kc = ks * 16 + 2 * tig;
        u32 bh[2][2];
#pragma unroll
        for (int j = 0; j < 2; ++j) {
            const char* b = sm + M8B1 + ((njb + j) * 8 + gq) * 528 + kc * 2;
            bh[j][0] = *(const u32*)b;
            bh[j][1] = *(const u32*)(b + 16);
        }
#pragma unroll
        for (int m = 0; m < 10; ++m) {
            u32 ah[4];
            const char* Ab = sm + M8A1 + (m * 16) * 528;
            ah[0] = *(const u32*)(Ab + gq * 528 + kc * 2);
            ah[1] = *(const u32*)(Ab + (gq + 8) * 528 + kc * 2);
            ah[2] = *(const u32*)(Ab + gq * 528 + (kc + 8) * 2);
            ah[3] = *(const u32*)(Ab + (gq + 8) * 528 + (kc + 8) * 2);
#pragma unroll
            for (int j = 0; j < 2; ++j)
                mma_f16(acc[m][j], ah, bh[j][0], bh[j][1]);
        }
    }
    __syncthreads();

#pragma unroll
    for (int m = 0; m < 10; ++m) {
        int rA = m * 16 + gq;
#pragma unroll
        for (int j = 0; j < 2; ++j) {
            int c0 = (njb + j) * 8 + 2 * tig;
            float bb0 = __ldg(nb1 + c0), bb1 = __ldg(nb1 + c0 + 1);
            *(u32*)(sm + M8A2 + rA * 272 + c0 * 2) =
                pack_h2(siluf(acc[m][j][0] + bb0), siluf(acc[m][j][1] + bb1));
            *(u32*)(sm + M8A2 + (rA + 8) * 272 + c0 * 2) =
                pack_h2(siluf(acc[m][j][2] + bb0), siluf(acc[m][j][3] + bb1));
        }
    }
    {
        const u32* src2 = (const u32*)(g_nw2 + L * 16384);
        for (int idx = tid; idx < 8192; idx += 256) {
            int n = idx >> 6, k2 = idx & 63;
            *(u32*)(sm + M8B2 + n * 272 + k2 * 4) = src2[idx];
        }
        if (has_next) {
            const u32* srcW = (const u32*)(g_w1n + (L + 1) * 32768);
            for (int idx = tid; idx < 16384; idx += 256) {
                int n = idx >> 6, k2 = idx & 63;
                *(u32*)(sm + M8WN + n * 272 + k2 * 4) = srcW[idx];
            }
        }
    }
    __syncthreads();

    float acc2[10][2][4];
#pragma unroll
    for (int m = 0; m < 10; ++m)
#pragma unroll
        for (int j = 0; j < 2; ++j)
            acc2[m][j][0] = acc2[m][j][1] = acc2[m][j][2] = acc2[m][j][3] = 0.f;
#pragma unroll
    for (int ks = 0; ks < 8; ++ks) {
        int kc = ks * 16 + 2 * tig;
        u32 bh[2][2];
#pragma unroll
        for (int j = 0; j < 2; ++j) {
            const char* b = sm + M8B2 + ((njb + j) * 8 + gq) * 272 + kc * 2;
            bh[j][0] = *(const u32*)b;
            bh[j][1] = *(const u32*)(b + 16);
        }
#pragma unroll
        for (int m = 0; m < 10; ++m) {
            u32 ah[4];
            const char* Ab = sm + M8A2 + (m * 16) * 272;
            ah[0] = *(const u32*)(Ab + gq * 272 + kc * 2);
            ah[1] = *(const u32*)(Ab + (gq + 8) * 272 + kc * 2);
            ah[2] = *(const u32*)(Ab + gq * 272 + (kc + 8) * 2);
            ah[3] = *(const u32*)(Ab + (gq + 8) * 272 + (kc + 8) * 2);
#pragma unroll
            for (int j = 0; j < 2; ++j)
                mma_f16(acc2[m][j], ah, bh[j][0], bh[j][1]);
        }
    }
    __syncthreads();

#pragma unroll
    for (int m = 0; m < 10; ++m) {
        int rA = m * 16 + gq, rB = rA + 8;
#pragma unroll
        for (int j = 0; j < 2; ++j) {
            int c0 = (njb + j) * 8 + 2 * tig;
            float bb0 = __ldg(nb2 + c0), bb1 = __ldg(nb2 + c0 + 1);
            {
                float* d = g_h + ((size_t)gb * 160 + rA) * 128 + c0;
                float2 o = *(float2*)d;
                o.x += siluf(acc2[m][j][0] + bb0);
                o.y += siluf(acc2[m][j][1] + bb1);
                *(float2*)d = o;
                if (has_next)
                    *(u32*)(sm + M8A2 + rA * 272 + c0 * 2) = pack_h2(o.x, o.y);
            }
            {
                float* d = g_h + ((size_t)gb * 160 + rB) * 128 + c0;
                float2 o = *(float2*)d;
                o.x += siluf(acc2[m][j][2] + bb0);
                o.y += siluf(acc2[m][j][3] + bb1);
                *(float2*)d = o;
                if (has_next)
                    *(u32*)(sm + M8A2 + rB * 272 + c0 * 2) = pack_h2(o.x, o.y);
            }
        }
    }
    if (!has_next) return;
    __syncthreads();

    int nj3 = w * 4;
#pragma unroll
    for (int mh = 0; mh < 2; ++mh) {
        float acc3[5][4][4];
#pragma unroll
        for (int m = 0; m < 5; ++m)
#pragma unroll
            for (int j = 0; j < 4; ++j)
                acc3[m][j][0] = acc3[m][j][1] = acc3[m][j][2] = acc3[m][j][3] = 0.f;
#pragma unroll
        for (int ks = 0; ks < 8; ++ks) {
            int kc = ks * 16 + 2 * tig;
            u32 bh[4][2];
#pragma unroll
            for (int j = 0; j < 4; ++j) {
                const char* b = sm + M8WN + ((nj3 + j) * 8 + gq) * 272 + kc * 2;
                bh[j][0] = *(const u32*)b;
                bh[j][1] = *(const u32*)(b + 16);
            }
#pragma unroll
            for (int m = 0; m < 5; ++m) {
                u32 ah[4];
                const char* Ab = sm + M8A2 + ((mh * 5 + m) * 16) * 272;
                ah[0] = *(const u32*)(Ab + gq * 272 + kc * 2);
                ah[1] = *(const u32*)(Ab + (gq + 8) * 272 + kc * 2);
                ah[2] = *(const u32*)(Ab + gq * 272 + (kc + 8) * 2);
                ah[3] = *(const u32*)(Ab + (gq + 8) * 272 + (kc + 8) * 2);
#pragma unroll
                for (int j = 0; j < 4; ++j)
                    mma_f16(acc3[m][j], ah, bh[j][0], bh[j][1]);
            }
        }
#pragma unroll
        for (int m = 0; m < 5; ++m) {
            int rowA = (mh * 5 + m) * 16 + gq, rowB = rowA + 8;
#pragma unroll
            for (int j = 0; j < 4; ++j) {
                int n = (nj3 + j) * 8 + 2 * tig;
                size_t baseA = ((size_t)gb * 160 + rowA) * 128;
                size_t baseB = ((size_t)gb * 160 + rowB) * 128;
                float* dA = (n < 128) ? (g_hs + baseA + n) : (g_hd + baseA + n - 128);
                float* dB = (n < 128) ? (g_hs + baseB + n) : (g_hd + baseB + n - 128);
                *(float2*)dA = make_float2(acc3[m][j][0], acc3[m][j][1]);
                *(float2*)dB = make_float2(acc3[m][j][2], acc3[m][j][3]);
            }
        }
    }
}

// ---------------- output heads ----------------
__global__ __launch_bounds__(128) void k_final(
    const float* __restrict__ lattices, const float* __restrict__ coord_w,
    const float* __restrict__ lattice_w, float* __restrict__ out)
{
    __shared__ __align__(16) float hT[128 * 20];
    __shared__ float gf[128];
    __shared__ float pre[9];
    int g = blockIdx.x, tid = threadIdx.x;
    for (int n = 0; n < 20; ++n)
        hT[tid * 20 + n] = g_h[(g * 20 + n) * H_DIM + tid];
    __syncthreads();
    float s = 0.f;
#pragma unroll
    for (int n = 0; n < 20; ++n) s += hT[tid * 20 + n];
    gf[tid] = s * 0.05f;
    __syncthreads();
    if (tid < 9) {
        float acc = 0.f;
        for (int k = 0; k < 128; ++k) acc += gf[k] * lattice_w[k * 9 + tid];
        pre[tid] = acc;
    }
    __syncthreads();
    if (tid < 9) {
        int i = tid / 3, kk = tid % 3;
        float v = 0.f;
#pragma unroll
        for (int j = 0; j < 3; ++j)
            v += pre[i * 3 + j] * lattices[g * 9 + j * 3 + kk];
        out[g * 9 + tid] = v;
    }
    if (tid < 60) {
        int n = tid / 3, c = tid % 3;
        float acc = 0.f;
        for (int k = 0; k < 128; ++k) acc += hT[k * 20 + n] * coord_w[k * 3 + c];
        out[G_CNT * 9 + (g * 20 + n) * 3 + c] = acc;
    }
}

// ---------------- launch ----------------
extern "C" void kernel_launch(void* const* d_in, const int* in_sizes, int n_in,
                              void* d_out, int out_size) {
    const int*   atom_types = (const int*)d_in[0];
    const float* frac       = (const float*)d_in[1];
    const float* lattices   = (const float*)d_in[2];
    const float* t          = (const float*)d_in[3];
    const float* emb_table  = (const float*)d_in[7];
    const float* w_latent   = (const float*)d_in[8];
    const float* b_latent   = (const float*)d_in[9];
    const float* ew1        = (const float*)d_in[10];
    const float* eb1        = (const float*)d_in[11];
    const float* ew2        = (const float*)d_in[12];
    const float* eb2        = (const float*)d_in[13];
    const float* nw1        = (const float*)d_in[14];
    const float* nb1        = (const float*)d_in[15];
    const float* nw2        = (const float*)d_in[16];
    const float* nb2        = (const float*)d_in[17];
    const float* coord_w    = (const float*)d_in[18];
    const float* lattice_w  = (const float*)d_in[19];
    float* out = (float*)d_out;

    cudaFuncSetAttribute(k_edge_s, cudaFuncAttributeMaxDynamicSharedMemorySize, SM_TOT);
    cudaFuncSetAttribute(k_nodemlp_f, cudaFuncAttributeMaxDynamicSharedMemorySize, M8_TOT);
    cudaFuncSetAttribute(k_nodeside_t4, cudaFuncAttributeMaxDynamicSharedMemorySize, NS4_TOT);

    k_prep<<<(NLAYER * 106496 + 255) / 256, 256>>>(ew1, ew2, nw1, nw2);
    k_prep_emb<<<100, 128>>>(emb_table, w_latent);
    k_latip<<<G_CNT, 32>>>(lattices);
    k_latall<<<NLAYER * G_CNT * 128 / 256, 256>>>(ew1, eb1);
    k_embed<<<G_CNT, 128>>>(atom_types, t, w_latent, b_latent);
    k_dis<<<E_CNT / 128, 128>>>(frac);
    k_nodeside_t4<<<G_CNT / 4, 256, NS4_TOT>>>(0);
    for (int i = 0; i < NLAYER; ++i) {
        k_edge_s<<<EDGE_GRID, EW_THREADS, SM_TOT>>>(i, eb2 + i * 128);
        k_nodemlp_f<<<G_CNT / 8, 256, M8_TOT>>>(i, (i < NLAYER - 1) ? 1 : 0,
                                                nb1 + i * 128, nb2 + i * 128);
    }
    k_final<<<G_CNT, 128>>>(lattices, coord_w, lattice_w, out);
}

// round 16
// speedup vs baseline: 1.2784x; 1.0179x over previous
#include <cuda_runtime.h>
#include <cuda_bf16.h>
#include <cuda_fp16.h>
#include <math.h>
#include <stdint.h>

#define G_CNT 1024
#define A_CNT 20
#define N_CNT (G_CNT * A_CNT)
#define E_CNT (G_CNT * A_CNT * A_CNT)
#define H_DIM 128
#define NLAYER 4
#define EDGE_GRID 148
#define EW_THREADS 832

typedef unsigned long long u64;
typedef unsigned int u32;
typedef unsigned short u16;

// ---------------- scratch ----------------
__device__ float g_h[N_CNT * H_DIM];
__device__ float g_hs[N_CNT * H_DIM];
__device__ float g_hd[N_CNT * H_DIM];
__device__ float g_agg[N_CNT * H_DIM];
__device__ float g_latip[G_CNT * 9];
__device__ float g_latterm[NLAYER * G_CNT * H_DIM];
__device__ float g_embT[100 * H_DIM];
__device__ u16 g_disH[(size_t)E_CNT * 64];
__device__ u16 g_w1d[NLAYER * 128 * 64];
__device__ u16 g_w1n[NLAYER * 256 * 128];
__device__ u16 g_w2[NLAYER * 128 * 128];
__device__ u16 g_nw1[NLAYER * 128 * 256];
__device__ u16 g_nw2[NLAYER * 128 * 128];

__device__ __forceinline__ float siluf(float x) {
    return __fdividef(x, 1.0f + __expf(-x));
}
__device__ __forceinline__ u16 h_rn(float x) {
    return __half_as_ushort(__float2half_rn(x));
}
__device__ __forceinline__ u32 pack_h2(float a, float b) {
    __half2 hh = __floats2half2_rn(a, b);
    return *(u32*)&hh;
}
__device__ __forceinline__ void mma_f16(float c[4], const u32 a[4], u32 b0, u32 b1) {
    asm volatile(
        "mma.sync.aligned.m16n8k16.row.col.f32.f16.f16.f32 "
        "{%0,%1,%2,%3}, {%4,%5,%6,%7}, {%8,%9}, {%0,%1,%2,%3};"
        : "+f"(c[0]), "+f"(c[1]), "+f"(c[2]), "+f"(c[3])
        : "r"(a[0]), "r"(a[1]), "r"(a[2]), "r"(a[3]), "r"(b0), "r"(b1));
}

// ---------------- weight prep ----------------
__global__ __launch_bounds__(256) void k_prep(
    const float* __restrict__ ew1, const float* __restrict__ ew2,
    const float* __restrict__ nw1, const float* __restrict__ nw2)
{
    int i = blockIdx.x * 256 + threadIdx.x;
    if (i >= NLAYER * 106496) return;
    int L = i / 106496, j = i % 106496;
    const float* e1 = ew1 + L * 325 * 128;
    const float* e2 = ew2 + L * 128 * 128;
    const float* n1 = nw1 + L * 256 * 128;
    const float* n2 = nw2 + L * 128 * 128;
    if (j < 8192) {
        int n = j >> 6, k = j & 63;
        float v = (k < 60) ? e1[(265 + k) * 128 + n] : 0.f;
        g_w1d[L * 8192 + j] = h_rn(v);
    } else if (j < 40960) {
        int jj = j - 8192;
        int n = jj >> 7, k = jj & 127;
        float v = (n < 128) ? e1[k * 128 + n] : e1[(128 + k) * 128 + (n - 128)];
        g_w1n[L * 32768 + jj] = h_rn(v);
    } else if (j < 57344) {
        int jj = j - 40960;
        int n = jj >> 7, k = jj & 127;
        g_w2[L * 16384 + jj] = h_rn(e2[k * 128 + n]);
    } else if (j < 90112) {
        int jj = j - 57344;
        int n = jj >> 8, k = jj & 255;
        g_nw1[L * 32768 + jj] = h_rn(n1[k * 128 + n]);
    } else {
        int jj = j - 90112;
        int n = jj >> 7, k = jj & 127;
        g_nw2[L * 16384 + jj] = h_rn(n2[k * 128 + n]);
    }
}

__global__ __launch_bounds__(128) void k_prep_emb(
    const float* __restrict__ emb_table, const float* __restrict__ w_latent)
{
    int a = blockIdx.x, c = threadIdx.x;
    float s = 0.f;
#pragma unroll 4
    for (int k = 0; k < 128; ++k)
        s = fmaf(emb_table[a * 128 + k], w_latent[k * 128 + c], s);
    g_embT[a * 128 + c] = s;
}

__global__ void k_latip(const float* __restrict__ lattices) {
    int g = blockIdx.x, tid = threadIdx.x;
    if (tid < 9) {
        int i = tid / 3, k = tid % 3;
        float s = 0.f;
#pragma unroll
        for (int j = 0; j < 3; ++j)
            s += lattices[g * 9 + i * 3 + j] * lattices[g * 9 + k * 3 + j];
        g_latip[g * 9 + tid] = s;
    }
}

__global__ __launch_bounds__(256) void k_latall(
    const float* __restrict__ ew1, const float* __restrict__ eb1)
{
    int idx = blockIdx.x * 256 + threadIdx.x;
    int L = idx >> 17;
    int g = (idx >> 7) & (G_CNT - 1);
    int c = idx & 127;
    float lt = eb1[L * 128 + c];
#pragma unroll
    for (int j = 0; j < 9; ++j)
        lt += g_latip[g * 9 + j] * ew1[L * 325 * 128 + (256 + j) * 128 + c];
    g_latterm[idx] = lt;
}

__global__ __launch_bounds__(128) void k_dis(const float* __restrict__ fc) {
    __shared__ u32 hiS[128 * 33];
    int tid = threadIdx.x;
    size_t e0 = (size_t)blockIdx.x * 128;
    int e = (int)e0 + tid;
    int g = e / 400, r = e % 400;
    int src = g * 20 + r / 20;
    int dst = g * 20 + r % 20;
    u16* hrow = (u16*)(hiS + tid * 33);
#pragma unroll
    for (int c = 0; c < 3; ++c) {
        float d = fc[dst * 3 + c] - fc[src * 3 + c];
        d -= floorf(d);
        float s1, c1;
        sincospif(2.0f * d, &s1, &c1);
        float s = 0.f, co = 1.f;
        hrow[c * 10] = 0;
        hrow[30 + c * 10] = h_rn(1.f);
#pragma unroll
        for (int f = 1; f < 10; ++f) {
            float ns = s * c1 + co * s1;
            float nc = co * c1 - s * s1;
            s = ns; co = nc;
            hrow[c * 10 + f] = h_rn(s);
            hrow[30 + c * 10 + f] = h_rn(co);
        }
    }
#pragma unroll
    for (int k = 60; k < 64; ++k) hrow[k] = 0;
    __syncthreads();
    u32* gh = (u32*)g_disH + e0 * 32;
    for (int i = tid; i < 4096; i += 128)
        gh[i] = hiS[(i >> 5) * 33 + (i & 31)];
}

__global__ __launch_bounds__(128) void k_embed(
    const int* __restrict__ atom_types, const float* __restrict__ t,
    const float* __restrict__ w_latent, const float* __restrict__ b_latent)
{
    __shared__ int at[20];
    __shared__ float ts[256];
    int g = blockIdx.x, c = threadIdx.x;
    if (c < 20) at[c] = atom_types[g * 20 + c];
    ts[c] = t[g * 256 + c];
    ts[c + 128] = t[g * 256 + c + 128];
    __syncthreads();
    float t0 = b_latent[c], t1 = 0.f, t2 = 0.f, t3 = 0.f;
#pragma unroll 8
    for (int k = 0; k < 256; k += 4) {
        t0 = fmaf(ts[k],     w_latent[(128 + k) * 128 + c], t0);
        t1 = fmaf(ts[k + 1], w_latent[(129 + k) * 128 + c], t1);
        t2 = fmaf(ts[k + 2], w_latent[(130 + k) * 128 + c], t2);
        t3 = fmaf(ts[k + 3], w_latent[(131 + k) * 128 + c], t3);
    }
    float tl = (t0 + t1) + (t2 + t3);
#pragma unroll
    for (int n = 0; n < 20; ++n)
        g_h[(g * 20 + n) * H_DIM + c] = g_embT[at[n] * 128 + c] + tl;
}

// ---------------- tensor nodeside (layer 0 only), 4 graphs/block ----------
#define NS4A 0
#define NS4B 21760
#define NS4_TOT 91392

__global__ __launch_bounds__(256, 2) void k_nodeside_t4(int L)
{
    extern __shared__ char sm[];
    int gb = blockIdx.x, tid = threadIdx.x;
    int w = tid >> 5, lane = tid & 31;
    int gq = lane >> 2, tig = lane & 3;

    for (int idx = tid; idx < 5120; idx += 256) {
        int r = idx >> 6, c2 = idx & 63;
        const float* src = g_h + ((size_t)gb * 80 + r) * 128 + c2 * 2;
        *(u32*)(sm + NS4A + r * 272 + c2 * 4) = pack_h2(src[0], src[1]);
    }
    {
        const u32* src = (const u32*)(g_w1n + L * 32768);
        for (int idx = tid; idx < 16384; idx += 256) {
            int n = idx >> 6, k2 = idx & 63;
            *(u32*)(sm + NS4B + n * 272 + k2 * 4) = src[idx];
        }
    }
    __syncthreads();

    int njb = w * 4;
    float acc[5][4][4];
#pragma unroll
    for (int m = 0; m < 5; ++m)
#pragma unroll
        for (int j = 0; j < 4; ++j)
            acc[m][j][0] = acc[m][j][1] = acc[m][j][2] = acc[m][j][3] = 0.f;
#pragma unroll
    for (int ks = 0; ks < 8; ++ks) {
        int kc = ks * 16 + 2 * tig;
        u32 bh[4][2];
#pragma unroll
        for (int j = 0; j < 4; ++j) {
            const char* b = sm + NS4B + ((njb + j) * 8 + gq) * 272 + kc * 2;
            bh[j][0] = *(const u32*)b;
            bh[j][1] = *(const u32*)(b + 16);
        }
#pragma unroll
        for (int m = 0; m < 5; ++m) {
            u32 ah[4];
            const char* Ab = sm + NS4A + (m * 16) * 272;
            ah[0] = *(const u32*)(Ab + gq * 272 + kc * 2);
            ah[1] = *(const u32*)(Ab + (gq + 8) * 272 + kc * 2);
            ah[2] = *(const u32*)(Ab + gq * 272 + (kc + 8) * 2);
            ah[3] = *(const u32*)(Ab + (gq + 8) * 272 + (kc + 8) * 2);
#pragma unroll
            for (int j = 0; j < 4; ++j)
                mma_f16(acc[m][j], ah, bh[j][0], bh[j][1]);
        }
    }
#pragma unroll
    for (int m = 0; m < 5; ++m) {
        int rowA = m * 16 + gq, rowB = rowA + 8;
#pragma unroll
        for (int j = 0; j < 4; ++j) {
            int n = (njb + j) * 8 + 2 * tig;
            size_t baseA = ((size_t)gb * 80 + rowA) * 128;
            size_t baseB = ((size_t)gb * 80 + rowB) * 128;
            float* dA = (n < 128) ? (g_hs + baseA + n) : (g_hd + baseA + n - 128);
            float* dB = (n < 128) ? (g_hs + baseB + n) : (g_hd + baseB + n - 128);
            *(float2*)dA = make_float2(acc[m][j][0], acc[m][j][1]);
            *(float2*)dB = make_float2(acc[m][j][2], acc[m][j][3]);
        }
    }
}

// ---------------- persistent edge kernel: 26 warps, 1 tile/warp,
//                  warp 25 prefetches next graph's hs/hd (double-buffered) --
#define SW1 0           // 18432
#define SW2 18432       // -> 53248
#define SAW 53248       // 25 x 4352 -> 162048
#define SHS0 162048
#define SHD0 172288
#define SHS1 182528
#define SHD1 192768
#define SB2 203008
#define SPART 203520    // -> 229120
#define SM_TOT 229120

__global__ __launch_bounds__(EW_THREADS, 1) void k_edge_s(
    int L, const float* __restrict__ eb2)
{
    extern __shared__ char sm[];
    int tid = threadIdx.x;
    int w = tid >> 5, lane = tid & 31;
    int gq = lane >> 2, tig = lane & 3;

    {
        const u32* src = (const u32*)(g_w1d + L * 8192);
        for (int idx = tid; idx < 4096; idx += EW_THREADS) {
            int n = idx >> 5, k2 = idx & 31;
            *(u32*)(sm + SW1 + n * 144 + k2 * 4) = src[idx];
        }
        const u32* src2 = (const u32*)(g_w2 + L * 16384);
        for (int idx = tid; idx < 8192; idx += EW_THREADS) {
            int n = idx >> 6, k2 = idx & 63;
            *(u32*)(sm + SW2 + n * 272 + k2 * 4) = src2[idx];
        }
        if (tid < 128) ((float*)(sm + SB2))[tid] = eb2[tid];
    }

    float* b2 = (float*)(sm + SB2);
    float* part = (float*)(sm + SPART);
    char* AB = sm + SAW + w * 4352;
    const float* lat4 = g_latterm + (size_t)L * G_CNT * H_DIM;

    {
        int g0 = blockIdx.x;
        float* hs0 = (float*)(sm + SHS0);
        float* hd0 = (float*)(sm + SHD0);
        for (int i = tid; i < 2560; i += EW_THREADS) {
            hs0[i] = g_hs[(size_t)g0 * 2560 + i] + lat4[g0 * 128 + (i & 127)];
            hd0[i] = g_hd[(size_t)g0 * 2560 + i];
        }
    }
    __syncthreads();

    int pp = 0;
    for (int g0 = blockIdx.x; g0 < G_CNT; g0 += EDGE_GRID, pp ^= 1) {
        float* hs = (float*)(sm + (pp ? SHS1 : SHS0));
        float* hd = (float*)(sm + (pp ? SHD1 : SHD0));

        if (w < 25) {
            int e0 = w * 16;
            {
                const uint4* sH = (const uint4*)(g_disH + ((size_t)g0 * 400 + e0) * 64);
#pragma unroll
                for (int q = 0; q < 4; ++q) {
                    int idx = lane + q * 32;
                    int row = idx >> 3, seg = idx & 7;
                    *(uint4*)(AB + row * 144 + seg * 16) = sH[row * 8 + seg];
                }
            }
            __syncwarp();
            u32 fr[4][4];
#pragma unroll
            for (int ks = 0; ks < 4; ++ks) {
                int kc = ks * 16 + 2 * tig;
                fr[ks][0] = *(const u32*)(AB + gq * 144 + kc * 2);
                fr[ks][1] = *(const u32*)(AB + (gq + 8) * 144 + kc * 2);
                fr[ks][2] = *(const u32*)(AB + gq * 144 + (kc + 8) * 2);
                fr[ks][3] = *(const u32*)(AB + (gq + 8) * 144 + (kc + 8) * 2);
            }
            __syncwarp();

            int eA = e0 + gq, eB = e0 + gq + 8;
            int srcA = eA / 20, dstA = eA - srcA * 20;
            int srcB = eB / 20, dstB = eB - srcB * 20;

#pragma unroll
            for (int nh = 0; nh < 2; ++nh) {
                float acc[8][4];
#pragma unroll
                for (int j = 0; j < 8; ++j)
                    acc[j][0] = acc[j][1] = acc[j][2] = acc[j][3] = 0.f;
#pragma unroll
                for (int ks = 0; ks < 4; ++ks) {
                    int kc = ks * 16 + 2 * tig;
#pragma unroll
                    for (int j = 0; j < 8; ++j) {
                        const char* bh = sm + SW1 + (((nh * 8 + j) * 8 + gq) * 72 + kc) * 2;
                        mma_f16(acc[j], fr[ks], *(const u32*)bh, *(const u32*)(bh + 16));
                    }
                }
#pragma unroll
                for (int j = 0; j < 8; ++j) {
                    int c0 = (nh * 8 + j) * 8 + 2 * tig;
                    float2 hsA = *(const float2*)&hs[srcA * 128 + c0];
                    float2 hdA = *(const float2*)&hd[dstA * 128 + c0];
                    float2 hsB = *(const float2*)&hs[srcB * 128 + c0];
                    float2 hdB = *(const float2*)&hd[dstB * 128 + c0];
                    float x0 = siluf(acc[j][0] + hsA.x + hdA.x);
                    float x1 = siluf(acc[j][1] + hsA.y + hdA.y);
                    float x2 = siluf(acc[j][2] + hsB.x + hdB.x);
                    float x3 = siluf(acc[j][3] + hsB.y + hdB.y);
                    *(u32*)(AB + gq * 272 + c0 * 2) = pack_h2(x0, x1);
                    *(u32*)(AB + (gq + 8) * 272 + c0 * 2) = pack_h2(x2, x3);
                }
            }
            __syncwarp();

            int sA = e0 / 20;
            int bnd = 20 * (sA + 1) - e0;
            if (bnd > 16) bnd = 16;
            bool lo = gq < bnd, hi = (gq + 8) < bnd;
#pragma unroll
            for (int nh = 0; nh < 2; ++nh) {
                float acc2[8][4];
#pragma unroll
                for (int j = 0; j < 8; ++j)
                    acc2[j][0] = acc2[j][1] = acc2[j][2] = acc2[j][3] = 0.f;
#pragma unroll
                for (int ks = 0; ks < 8; ++ks) {
                    int kc = ks * 16 + 2 * tig;
                    u32 ah[4];
                    ah[0] = *(const u32*)(AB + gq * 272 + kc * 2);
                    ah[1] = *(const u32*)(AB + (gq + 8) * 272 + kc * 2);
                    ah[2] = *(const u32*)(AB + gq * 272 + (kc + 8) * 2);
                    ah[3] = *(const u32*)(AB + (gq + 8) * 272 + (kc + 8) * 2);
#pragma unroll
                    for (int j = 0; j < 8; ++j) {
                        const char* bh = sm + SW2 + (((nh * 8 + j) * 8 + gq) * 136 + kc) * 2;
                        mma_f16(acc2[j], ah, *(const u32*)bh, *(const u32*)(bh + 16));
                    }
                }
#pragma unroll
                for (int j = 0; j < 8; ++j) {
                    int c0 = (nh * 8 + j) * 8 + 2 * tig;
                    float2 bb = *(const float2*)&b2[c0];
                    float v0 = siluf(acc2[j][0] + bb.x);
                    float v1 = siluf(acc2[j][1] + bb.y);
                    float v2 = siluf(acc2[j][2] + bb.x);
                    float v3 = siluf(acc2[j][3] + bb.y);
                    float p0x = (lo ? v0 : 0.f) + (hi ? v2 : 0.f);
                    float p0y = (lo ? v1 : 0.f) + (hi ? v3 : 0.f);
                    float p1x = (lo ? 0.f : v0) + (hi ? 0.f : v2);
                    float p1y = (lo ? 0.f : v1) + (hi ? 0.f : v3);
#pragma unroll
                    for (int off = 4; off <= 16; off <<= 1) {
                        p0x += __shfl_xor_sync(0xFFFFFFFF, p0x, off);
                        p0y += __shfl_xor_sync(0xFFFFFFFF, p0y, off);
                        p1x += __shfl_xor_sync(0xFFFFFFFF, p1x, off);
                        p1y += __shfl_xor_sync(0xFFFFFFFF, p1y, off);
                    }
                    if (gq == 0) {
                        part[w * 256 + c0] = p0x;
                        part[w * 256 + c0 + 1] = p0y;
                        part[w * 256 + 128 + c0] = p1x;
                        part[w * 256 + 128 + c0 + 1] = p1y;
                    }
                }
            }
        } else {
            int gn = g0 + EDGE_GRID;
            if (gn < G_CNT) {
                float* hsn = (float*)(sm + (pp ? SHS0 : SHS1));
                float* hdn = (float*)(sm + (pp ? SHD0 : SHD1));
                for (int i = lane; i < 2560; i += 32) {
                    hsn[i] = g_hs[(size_t)gn * 2560 + i] + lat4[gn * 128 + (i & 127)];
                    hdn[i] = g_hd[(size_t)gn * 2560 + i];
                }
            }
        }
        __syncthreads();

        for (int idx = tid; idx < 2560; idx += EW_THREADS) {
            int s = idx >> 7, c = idx & 127;
            int t0 = (20 * s) >> 4, t1 = (20 * s + 19) >> 4;
            float a = 0.f;
            for (int t = t0; t <= t1; ++t) {
                int sA2 = (16 * t) / 20;
                int sB2 = (16 * t + 15) / 20;
                if (sA2 == s) a += part[t * 256 + c];
                else if (sB2 == s) a += part[t * 256 + 128 + c];
            }
            g_agg[(size_t)g0 * 2560 + idx] = a * 0.05f;
        }
        __syncthreads();
    }
}

// ---------------- fused node MLP + next-layer nodeside, 8 graphs/block,
//                  512 threads (16 warps, 1 n-tile per warp) ----------------
#define M8A1 0
#define M8B1 84480
#define M8A2 0
#define M8B2 43520
#define M8WN 78336
#define M8_TOT 152064

__global__ __launch_bounds__(512, 1) void k_nodemlp_f(
    int L, int has_next,
    const float* __restrict__ nb1, const float* __restrict__ nb2)
{
    extern __shared__ char sm[];
    int gb = blockIdx.x, tid = threadIdx.x;
    int w = tid >> 5, lane = tid & 31;
    int gq = lane >> 2, tig = lane & 3;

    for (int idx = tid; idx < 20480; idx += 512) {
        int r = idx >> 7, c2 = idx & 127;
        float a0, a1;
        size_t base = ((size_t)gb * 160 + r) * 128;
        if (c2 < 64) {
            const float* s = g_h + base + c2 * 2;
            a0 = s[0]; a1 = s[1];
        } else {
            const float* s = g_agg + base + (c2 - 64) * 2;
            a0 = s[0]; a1 = s[1];
        }
        *(u32*)(sm + M8A1 + r * 528 + c2 * 4) = pack_h2(a0, a1);
    }
    {
        const u32* src = (const u32*)(g_nw1 + L * 32768);
        for (int idx = tid; idx < 16384; idx += 512) {
            int n = idx >> 7, k2 = idx & 127;
            *(u32*)(sm + M8B1 + n * 528 + k2 * 4) = src[idx];
        }
    }
    __syncthreads();

    // GEMM1: each warp owns n-tile w (16 warps = 16 n-tiles), 10 m-tiles
    float acc[10][4];
#pragma unroll
    for (int m = 0; m < 10; ++m)
        acc[m][0] = acc[m][1] = acc[m][2] = acc[m][3] = 0.f;
#pragma unroll
    for (int ks = 0; ks < 16; ++ks) {
        int kc = ks * 16 + 2 * tig;
        const char* b = sm + M8B1 + (w * 8 + gq) * 528 + kc * 2;
        u32 b0 = *(const u32*)b, b1 = *(const u32*)(b + 16);
#pragma unroll
        for (int m = 0; m < 10; ++m) {
            u32 ah[4];
            const char* Ab = sm + M8A1 + (m * 16) * 528;
            ah[0] = *(const u32*)(Ab + gq * 528 + kc * 2);
            ah[1] = *(const u32*)(Ab + (gq + 8) * 528 + kc * 2);
            ah[2] = *(const u32*)(Ab + gq * 528 + (kc + 8) * 2);
            ah[3] = *(const u32*)(Ab + (gq + 8) * 528 + (kc + 8) * 2);
            mma_f16(acc[m], ah, b0, b1);
        }
    }
    __syncthreads();   // A1/B1 dead

    // epilogue 1 -> A2; stage B2; stage WN
#pragma unroll
    for (int m = 0; m < 10; ++m) {
        int rA = m * 16 + gq;
        int c0 = w * 8 + 2 * tig;
        float bb0 = __ldg(nb1 + c0), bb1 = __ldg(nb1 + c0 + 1);
        *(u32*)(sm + M8A2 + rA * 272 + c0 * 2) =
            pack_h2(siluf(acc[m][0] + bb0), siluf(acc[m][1] + bb1));
        *(u32*)(sm + M8A2 + (rA + 8) * 272 + c0 * 2) =
            pack_h2(siluf(acc[m][2] + bb0), siluf(acc[m][3] + bb1));
    }
    {
        const u32* src2 = (const u32*)(g_nw2 + L * 16384);
        for (int idx = tid; idx < 8192; idx += 512) {
            int n = idx >> 6, k2 = idx & 63;
            *(u32*)(sm + M8B2 + n * 272 + k2 * 4) = src2[idx];
        }
        if (has_next) {
            const u32* srcW = (const u32*)(g_w1n + (L + 1) * 32768);
            for (int idx = tid; idx < 16384; idx += 512) {
                int n = idx >> 6, k2 = idx & 63;
                *(u32*)(sm + M8WN + n * 272 + k2 * 4) = srcW[idx];
            }
        }
    }
    __syncthreads();

    // GEMM2: warp w owns n-tile w, 10 m-tiles
    float acc2[10][4];
#pragma unroll
    for (int m = 0; m < 10; ++m)
        acc2[m][0] = acc2[m][1] = acc2[m][2] = acc2[m][3] = 0.f;
#pragma unroll
    for (int ks = 0; ks < 8; ++ks) {
        int kc = ks * 16 + 2 * tig;
        const char* b = sm + M8B2 + (w * 8 + gq) * 272 + kc * 2;
        u32 b0 = *(const u32*)b, b1 = *(const u32*)(b + 16);
#pragma unroll
        for (int m = 0; m < 10; ++m) {
            u32 ah[4];
            const char* Ab = sm + M8A2 + (m * 16) * 272;
            ah[0] = *(const u32*)(Ab + gq * 272 + kc * 2);
            ah[1] = *(const u32*)(Ab + (gq + 8) * 272 + kc * 2);
            ah[2] = *(const u32*)(Ab + gq * 272 + (kc + 8) * 2);
            ah[3] = *(const u32*)(Ab + (gq + 8) * 272 + (kc + 8) * 2);
            mma_f16(acc2[m], ah, b0, b1);
        }
    }
    __syncthreads();   // A2 reads done -> safe to overwrite with hA

    // epilogue 2: h += silu(acc2 + nb2) -> gmem + hA (fp16, A2 region)
#pragma unroll
    for (int m = 0; m < 10; ++m) {
        int rA = m * 16 + gq, rB = rA + 8;
        int c0 = w * 8 + 2 * tig;
        float bb0 = __ldg(nb2 + c0), bb1 = __ldg(nb2 + c0 + 1);
        {
            float* d = g_h + ((size_t)gb * 160 + rA) * 128 + c0;
            float2 o = *(float2*)d;
            o.x += siluf(acc2[m][0] + bb0);
            o.y += siluf(acc2[m][1] + bb1);
            *(float2*)d = o;
            if (has_next)
                *(u32*)(sm + M8A2 + rA * 272 + c0 * 2) = pack_h2(o.x, o.y);
        }
        {
            float* d = g_h + ((size_t)gb * 160 + rB) * 128 + c0;
            float2 o = *(float2*)d;
            o.x += siluf(acc2[m][2] + bb0);
            o.y += siluf(acc2[m][3] + bb1);
            *(float2*)d = o;
            if (has_next)
                *(u32*)(sm + M8A2 + rB * 272 + c0 * 2) = pack_h2(o.x, o.y);
        }
    }
    if (!has_next) return;
    __syncthreads();

    // GEMM3: hA[160,128] @ WN[128,256] -> hs|hd; 32 n-tiles / 16 warps = 2 each
    int nj3 = w * 2;
#pragma unroll
    for (int mh = 0; mh < 2; ++mh) {
        float acc3[5][2][4];
#pragma unroll
        for (int m = 0; m < 5; ++m)
#pragma unroll
            for (int j = 0; j < 2; ++j)
                acc3[m][j][0] = acc3[m][j][1] = acc3[m][j][2] = acc3[m][j][3] = 0.f;
#pragma unroll
        for (int ks = 0; ks < 8; ++ks) {
            int kc = ks * 16 + 2 * tig;
            u32 bh[2][2];
#pragma unroll
            for (int j = 0; j < 2; ++j) {
                const char* b = sm + M8WN + ((nj3 + j) * 8 + gq) * 272 + kc * 2;
                bh[j][0] = *(const u32*)b;
                bh[j][1] = *(const u32*)(b + 16);
            }
#pragma unroll
            for (int m = 0; m < 5; ++m) {
                u32 ah[4];
                const char* Ab = sm + M8A2 + ((mh * 5 + m) * 16) * 272;
                ah[0] = *(const u32*)(Ab + gq * 272 + kc * 2);
                ah[1] = *(const u32*)(Ab + (gq + 8) * 272 + kc * 2);
                ah[2] = *(const u32*)(Ab + gq * 272 + (kc + 8) * 2);
                ah[3] = *(const u32*)(Ab + (gq + 8) * 272 + (kc + 8) * 2);
#pragma unroll
                for (int j = 0; j < 2; ++j)
                    mma_f16(acc3[m][j], ah, bh[j][0], bh[j][1]);
            }
        }
#pragma unroll
        for (int m = 0; m < 5; ++m) {
            int rowA = (mh * 5 + m) * 16 + gq, rowB = rowA + 8;
#pragma unroll
            for (int j = 0; j < 2; ++j) {
                int n = (nj3 + j) * 8 + 2 * tig;
                size_t baseA = ((size_t)gb * 160 + rowA) * 128;
                size_t baseB = ((size_t)gb * 160 + rowB) * 128;
                float* dA = (n < 128) ? (g_hs + baseA + n) : (g_hd + baseA + n - 128);
                float* dB = (n < 128) ? (g_hs + baseB + n) : (g_hd + baseB + n - 128);
                *(float2*)dA = make_float2(acc3[m][j][0], acc3[m][j][1]);
                *(float2*)dB = make_float2(acc3[m][j][2], acc3[m][j][3]);
            }
        }
    }
}

// ---------------- output heads ----------------
__global__ __launch_bounds__(128) void k_final(
    const float* __restrict__ lattices, const float* __restrict__ coord_w,
    const float* __restrict__ lattice_w, float* __restrict__ out)
{
    __shared__ __align__(16) float hT[128 * 20];
    __shared__ float gf[128];
    __shared__ float pre[9];
    int g = blockIdx.x, tid = threadIdx.x;
    for (int n = 0; n < 20; ++n)
        hT[tid * 20 + n] = g_h[(g * 20 + n) * H_DIM + tid];
    __syncthreads();
    float s = 0.f;
#pragma unroll
    for (int n = 0; n < 20; ++n) s += hT[tid * 20 + n];
    gf[tid] = s * 0.05f;
    __syncthreads();
    if (tid < 9) {
        float acc = 0.f;
        for (int k = 0; k < 128; ++k) acc += gf[k] * lattice_w[k * 9 + tid];
        pre[tid] = acc;
    }
    __syncthreads();
    if (tid < 9) {
        int i = tid / 3, kk = tid % 3;
        float v = 0.f;
#pragma unroll
        for (int j = 0; j < 3; ++j)
            v += pre[i * 3 + j] * lattices[g * 9 + j * 3 + kk];
        out[g * 9 + tid] = v;
    }
    if (tid < 60) {
        int n = tid / 3, c = tid % 3;
        float acc = 0.f;
        for (int k = 0; k < 128; ++k) acc += hT[k * 20 + n] * coord_w[k * 3 + c];
        out[G_CNT * 9 + (g * 20 + n) * 3 + c] = acc;
    }
}

// ---------------- launch ----------------
extern "C" void kernel_launch(void* const* d_in, const int* in_sizes, int n_in,
                              void* d_out, int out_size) {
    const int*   atom_types = (const int*)d_in[0];
    const float* frac       = (const float*)d_in[1];
    const float* lattices   = (const float*)d_in[2];
    const float* t          = (const float*)d_in[3];
    const float* emb_table  = (const float*)d_in[7];
    const float* w_latent   = (const float*)d_in[8];
    const float* b_latent   = (const float*)d_in[9];
    const float* ew1        = (const float*)d_in[10];
    const float* eb1        = (const float*)d_in[11];
    const float* ew2        = (const float*)d_in[12];
    const float* eb2        = (const float*)d_in[13];
    const float* nw1        = (const float*)d_in[14];
    const float* nb1        = (const float*)d_in[15];
    const float* nw2        = (const float*)d_in[16];
    const float* nb2        = (const float*)d_in[17];
    const float* coord_w    = (const float*)d_in[18];
    const float* lattice_w  = (const float*)d_in[19];
    float* out = (float*)d_out;

    cudaFuncSetAttribute(k_edge_s, cudaFuncAttributeMaxDynamicSharedMemorySize, SM_TOT);
    cudaFuncSetAttribute(k_nodemlp_f, cudaFuncAttributeMaxDynamicSharedMemorySize, M8_TOT);
    cudaFuncSetAttribute(k_nodeside_t4, cudaFuncAttributeMaxDynamicSharedMemorySize, NS4_TOT);

    k_prep<<<(NLAYER * 106496 + 255) / 256, 256>>>(ew1, ew2, nw1, nw2);
    k_prep_emb<<<100, 128>>>(emb_table, w_latent);
    k_latip<<<G_CNT, 32>>>(lattices);
    k_latall<<<NLAYER * G_CNT * 128 / 256, 256>>>(ew1, eb1);
    k_embed<<<G_CNT, 128>>>(atom_types, t, w_latent, b_latent);
    k_dis<<<E_CNT / 128, 128>>>(frac);
    k_nodeside_t4<<<G_CNT / 4, 256, NS4_TOT>>>(0);
    for (int i = 0; i < NLAYER; ++i) {
        k_edge_s<<<EDGE_GRID, EW_THREADS, SM_TOT>>>(i, eb2 + i * 128);
        k_nodemlp_f<<<G_CNT / 8, 512, M8_TOT>>>(i, (i < NLAYER - 1) ? 1 : 0,
                                                nb1 + i * 128, nb2 + i * 128);
    }
    k_final<<<G_CNT, 128>>>(lattices, coord_w, lattice_w, out);
}